// round 15
// baseline (speedup 1.0000x reference)
#include <cuda_runtime.h>
#include <cuda_fp16.h>
#include <math.h>
#include <stdint.h>

#define NB 256
#define NC 26
#define SXv 179
#define SYv 15
#define NP (SXv*SYv)          // 2685
#define MM 7
#define NMODE (14*MM)         // 98
#define KTOT (NC*NP)          // 69810
#define KPADH 69824           // padded to /64 (16B-aligned fp16 rows)
#define NH1 2808
#define NO 128
#define NCH32 2182            // ceil(69810/32)
#define SPLITK1 13

// ---------------- device scratch ----------------
__device__ float  g_h [NB*NC*NP];
__device__ float  g_t2[NB*NC*NP];
__device__ float2 g_F [NB*NC*NMODE];
__device__ float2 g_txf[14*SXv];
__device__ float2 g_txi[14*SXv];
__device__ float2 g_twyf[MM*SYv];
__device__ float2 g_twy2[MM*SYv];
__device__ float  g_ap [NB*NC];
__device__ float  g_att[NB];
__device__ float  g_Cp [SPLITK1*NB*NH1];
__device__ float  g_C  [NB*NH1];
__device__ float  g_x1 [NB*NO];
__device__ __half g_Ah[(size_t)NB*KPADH];    // 35.8 MB

// ---------------- host-side stream/event pack ----------------
struct SidePack {
    cudaStream_t s2;
    cudaEvent_t eFuse, eAtt;
    SidePack(){
        cudaStreamCreateWithFlags(&s2, cudaStreamNonBlocking);
        cudaEventCreateWithFlags(&eFuse, cudaEventDisableTiming);
        cudaEventCreateWithFlags(&eAtt,  cudaEventDisableTiming);
    }
};
static SidePack g_sp;

__device__ __forceinline__ float gelu_f(float x){
    return 0.5f*x*(1.0f + erff(x*0.70710678118654752f));
}

__device__ __forceinline__ uint32_t smem_u32(const void* p){
    uint32_t a;
    asm("{ .reg .u64 t; cvta.to.shared.u64 t, %1; cvt.u32.u64 %0, t; }" : "=r"(a) : "l"(p));
    return a;
}

__device__ __forceinline__ void block_reduce2(float s, float q, float* shm,
                                              float& osum, float& osq){
    int t = threadIdx.x, lane = t & 31, wid = t >> 5;
    #pragma unroll
    for (int o = 16; o > 0; o >>= 1){
        s += __shfl_down_sync(0xFFFFFFFFu, s, o);
        q += __shfl_down_sync(0xFFFFFFFFu, q, o);
    }
    if (lane == 0){ shm[wid] = s; shm[8 + wid] = q; }
    __syncthreads();
    if (t == 0){
        float ss = 0.f, qq = 0.f;
        #pragma unroll
        for (int i = 0; i < 8; i++){ ss += shm[i]; qq += shm[8 + i]; }
        shm[16] = ss; shm[17] = qq;
    }
    __syncthreads();
    osum = shm[16]; osq = shm[17];
}

// ---------------- twiddle tables + g_ap zero + g_Ah padding ----------------
__global__ void k_twiddle(){
    int i = blockIdx.x*blockDim.x + threadIdx.x;
    if (i < 14*SXv){
        int k1i = i/SXv, xx = i%SXv;
        int keff = (k1i < 7) ? k1i : (14 - k1i);
        float sn, cs;
        sincospif(2.0f*(float)(keff*xx)/179.0f, &sn, &cs);
        g_txf[i] = make_float2(cs, (k1i < 7) ? -sn : sn);
        g_txi[i] = make_float2(cs, (k1i < 7) ? sn : -sn);
    }
    if (i < MM*SYv){
        int k = i/SYv, y = i%SYv;
        float sn, cs;
        sincospif(2.0f*(float)(k*y)/15.0f, &sn, &cs);
        g_twyf[i] = make_float2(cs, -sn);
        g_twy2[i] = make_float2(2.f*cs, 2.f*sn);
    }
    if (i < NB*NC) g_ap[i] = 0.f;
    if (i < NB*(KPADH - KTOT)){
        int row = i/(KPADH - KTOT), col = KTOT + i%(KPADH - KTOT);
        g_Ah[(size_t)row*KPADH + col] = __float2half(0.f);
    }
}

// ---------------- fused lift + instance-norm + forward truncated DFT ----------------
__global__ void __launch_bounds__(256) k_fdft(const float* __restrict__ x,
                                              const float* __restrict__ pw,
                                              const float* __restrict__ pb,
                                              int first){
    int bc = blockIdx.x;
    __shared__ float  sp[NP];
    __shared__ float2 Ys[SXv*MM];
    __shared__ float2 Pp[2*NMODE];
    __shared__ float  red[18];
    int t = threadIdx.x;

    float s = 0.f, q = 0.f;
    if (first){
        int b = bc / NC, w = bc % NC;
        float w0 = pw[w*3+0], w1 = pw[w*3+1], w2 = pw[w*3+2], bb = pb[w];
        const float* xb = x + (size_t)b*SXv*(SYv+1);
        float* outp = g_h + (size_t)bc*NP;
        for (int p = t; p < NP; p += 256){
            int xi = p/SYv, yi = p%SYv;
            float u = xb[xi*(SYv+1) + yi];
            float v = u*w0 + ((float)xi*(1.0f/178.0f))*w1 + ((float)yi*(1.0f/14.0f))*w2 + bb;
            outp[p] = v;
            sp[p] = v;
            s += v; q += v*v;
        }
    } else {
        const float* src = g_h + (size_t)bc*NP;
        for (int p = t; p < NP; p += 256){
            float v = src[p];
            sp[p] = v;
            s += v; q += v*v;
        }
    }
    __syncthreads();
    float sum, sq;
    block_reduce2(s, q, red, sum, sq);
    float mu  = sum * (1.0f/NP);
    float var = sq * (1.0f/NP) - mu*mu;
    float inv = rsqrtf(var + 1e-5f);
    for (int p = t; p < NP; p += 256) sp[p] = (sp[p] - mu)*inv;
    __syncthreads();

    for (int idx = t; idx < SXv*MM; idx += 256){
        int xx = idx/MM, k2 = idx%MM;
        float re = 0.f, im = 0.f;
        #pragma unroll
        for (int y = 0; y < SYv; y++){
            float2 tw = g_twyf[k2*SYv + y];
            float v = sp[xx*SYv + y];
            re = fmaf(v, tw.x, re);
            im = fmaf(v, tw.y, im);
        }
        Ys[idx] = make_float2(re, im);
    }
    __syncthreads();

    if (t < 2*NMODE){
        int mode = t >> 1, half = t & 1;
        int k1i = mode/MM, k2 = mode%MM;
        const float2* tw = g_txf + k1i*SXv;
        int xa = half ? 90 : 0, xbnd = half ? SXv : 90;
        float re = 0.f, im = 0.f;
        #pragma unroll 3
        for (int xx = xa; xx < xbnd; xx++){
            float2 u = tw[xx];
            float2 y = Ys[xx*MM + k2];
            re += y.x*u.x - y.y*u.y;
            im += y.x*u.y + y.y*u.x;
        }
        Pp[t] = make_float2(re, im);
    }
    __syncthreads();
    if (t < NMODE){
        float2 a = Pp[2*t], b2 = Pp[2*t+1];
        g_F[(size_t)bc*NMODE + t] = make_float2(a.x + b2.x, a.y + b2.y);
    }
}

// =====================================================================
// Merged k_idft: per-(b,o) channel-mix + inverse DFT + instance norm.
// Dynamic smem, phase-aliased regions (41.7 KB).
// =====================================================================
#define ID_FS  0                       // float2[26*98] = 20384
#define ID_WS  20384                   // float2[26*98] = 20384
#define ID_GS  40768                   // float2[98]    = 784
#define ID_RED 41552                   // float[18]     = 72
#define ID_SS  0                       // alias of FS: float2[1253] = 10024
#define ID_PL  20384                   // alias of WS: float[2685] = 10740
#define ID_SMEM 41664

__global__ void __launch_bounds__(256) k_idft(const float* __restrict__ w1,
                                              const float* __restrict__ w2){
    extern __shared__ char ism[];
    float2* Fs = (float2*)(ism + ID_FS);
    float2* Ws = (float2*)(ism + ID_WS);
    float2* Gs = (float2*)(ism + ID_GS);
    float*  red= (float*)(ism + ID_RED);
    int bc = blockIdx.x;
    int b = bc / NC, o = bc % NC;
    int t = threadIdx.x;

    // load F[b,:,:] and weight slice for output o
    const float2* fsrc = g_F + (size_t)b*NC*NMODE;
    const float2* w1f = (const float2*)w1;
    const float2* w2f = (const float2*)w2;
    for (int i = t; i < NC*NMODE; i += 256){
        Fs[i] = fsrc[i];
        int ci = i/NMODE, mode = i - ci*NMODE;
        int k1i = mode/MM, k2 = mode%MM;
        Ws[i] = (k1i < 7) ? w1f[(size_t)ci*(NC*49) + o*49 + k1i*7 + k2]
                          : w2f[(size_t)ci*(NC*49) + o*49 + (k1i-7)*7 + k2];
    }
    __syncthreads();

    // channel mix -> Gs (scaled)
    if (t < NMODE){
        float re = 0.f, im = 0.f;
        #pragma unroll 2
        for (int i = 0; i < NC; i++){
            float2 f = Fs[i*NMODE + t];
            float2 w = Ws[i*NMODE + t];
            re += f.x*w.x - f.y*w.y;
            im += f.x*w.y + f.y*w.x;
        }
        Gs[t] = make_float2(re*(1.0f/(179.0f*15.0f)), im*(1.0f/(179.0f*15.0f)));
    }
    __syncthreads();

    // x-expansion (Ss aliases Fs region — Fs no longer needed)
    float2* Ss = (float2*)(ism + ID_SS);
    for (int idx = t; idx < SXv*MM; idx += 256){
        int n1 = idx/MM, k2 = idx%MM;
        float re = 0.f, im = 0.f;
        #pragma unroll
        for (int k1i = 0; k1i < 14; k1i++){
            float2 g = Gs[k1i*MM + k2];
            float2 u = g_txi[k1i*SXv + n1];
            re += g.x*u.x - g.y*u.y;
            im += g.x*u.y + g.y*u.x;
        }
        Ss[idx] = make_float2(re, im);
    }
    __syncthreads();

    // y C2R + stats (pl aliases Ws region)
    float* pl = (float*)(ism + ID_PL);
    float s = 0.f, q = 0.f;
    for (int p = t; p < NP; p += 256){
        int n1 = p/SYv, n2 = p%SYv;
        float val = Ss[n1*MM].x;
        #pragma unroll
        for (int k2 = 1; k2 < MM; k2++){
            float2 sv = Ss[n1*MM + k2];
            float2 tw = g_twy2[k2*SYv + n2];
            val += sv.x*tw.x - sv.y*tw.y;
        }
        pl[p] = val;
        s += val; q += val*val;
    }
    __syncthreads();
    float sum, sq;
    block_reduce2(s, q, red, sum, sq);
    float mu  = sum * (1.0f/NP);
    float var = sq * (1.0f/NP) - mu*mu;
    float inv = rsqrtf(var + 1e-5f);
    float* d = g_t2 + (size_t)bc*NP;
    for (int p = t; p < NP; p += 256) d[p] = (pl[p] - mu)*inv;
}

// ---------------- fused: h = gelu( mlp(g_t2) + c1(h) ), optional fp16 A output ----------------
__global__ void __launch_bounds__(256) k_fuse(
        const float* __restrict__ w1, const float* __restrict__ b1,
        const float* __restrict__ w2, const float* __restrict__ b2,
        const float* __restrict__ wr, const float* __restrict__ br,
        int writeAh){
    __shared__ float sw1[NC*NC], sw2[NC*NC], swr[NC*NC], sb1[NC], sb2[NC], sbr[NC];
    int t = threadIdx.x;
    for (int i = t; i < NC*NC; i += 256){ sw1[i] = w1[i]; sw2[i] = w2[i]; swr[i] = wr[i]; }
    if (t < NC){ sb1[t] = b1[t]; sb2[t] = b2[t]; sbr[t] = br[t]; }
    __syncthreads();
    int p = blockIdx.x*256 + t;
    if (p >= NP) return;
    int b = blockIdx.y;
    size_t base = (size_t)b*NC*NP + p;
    float xin[NC], tm[NC];
    #pragma unroll
    for (int i = 0; i < NC; i++) xin[i] = g_t2[base + (size_t)i*NP];
    #pragma unroll
    for (int o = 0; o < NC; o++){
        float a = sb1[o];
        #pragma unroll
        for (int i = 0; i < NC; i++) a = fmaf(xin[i], sw1[o*NC+i], a);
        tm[o] = gelu_f(a);
    }
    float hin[NC];
    #pragma unroll
    for (int i = 0; i < NC; i++) hin[i] = g_h[base + (size_t)i*NP];
    __half* ahp = g_Ah + (size_t)b*KPADH + p;
    #pragma unroll
    for (int o = 0; o < NC; o++){
        float a = sb2[o] + sbr[o];
        #pragma unroll
        for (int i = 0; i < NC; i++) a = fmaf(tm[i],  sw2[o*NC+i], a);
        #pragma unroll
        for (int i = 0; i < NC; i++) a = fmaf(hin[i], swr[o*NC+i], a);
        float gv = gelu_f(a);
        g_h[base + (size_t)o*NP] = gv;
        if (writeAh) ahp[(size_t)o*NP] = __float2half(gv);
    }
}

// =====================================================================
// Tensor-core conv3x3 + relu + pooling (fused)
// =====================================================================
#define PADY 17
#define PPTOT (SXv*PADY)
#define CTM 128
#define NTILE 24
#define CROWS (CTM + 36)
#define XSTR 80
#define CV_XS 0
#define CV_WH (CROWS*XSTR)
#define CV_WL (CV_WH + 9*32*XSTR)
#define CV_RED (CV_WL + 9*32*XSTR)
#define CV_SMEM (CV_RED + 128)

#define LDSM4(R, ADDR) \
    asm volatile("ldmatrix.sync.aligned.m8n8.x4.shared.b16 {%0,%1,%2,%3}, [%4];" \
        : "=r"((R)[0]), "=r"((R)[1]), "=r"((R)[2]), "=r"((R)[3]) : "r"(ADDR))

#define MMA16816(D, A, B0, B1) \
    asm volatile("mma.sync.aligned.m16n8k16.row.col.f32.bf16.bf16.f32 " \
        "{%0,%1,%2,%3}, {%4,%5,%6,%7}, {%8,%9}, {%0,%1,%2,%3};" \
        : "+f"((D)[0]), "+f"((D)[1]), "+f"((D)[2]), "+f"((D)[3]) \
        : "r"((A)[0]), "r"((A)[1]), "r"((A)[2]), "r"((A)[3]), "r"(B0), "r"(B1))

#define MMAF16(D, A, B0, B1) \
    asm volatile("mma.sync.aligned.m16n8k16.row.col.f32.f16.f16.f32 " \
        "{%0,%1,%2,%3}, {%4,%5,%6,%7}, {%8,%9}, {%0,%1,%2,%3};" \
        : "+f"((D)[0]), "+f"((D)[1]), "+f"((D)[2]), "+f"((D)[3]) \
        : "r"((A)[0]), "r"((A)[1]), "r"((A)[2]), "r"((A)[3]), "r"(B0), "r"(B1))

#define CP16(dst, src) asm volatile("cp.async.cg.shared.global [%0], [%1], 16;" :: "r"(dst), "l"(src) : "memory")
#define CP_COMMIT() asm volatile("cp.async.commit_group;" ::: "memory")
#define CP_WAIT0()  asm volatile("cp.async.wait_group 0;" ::: "memory")
#define CP_WAIT1()  asm volatile("cp.async.wait_group 1;" ::: "memory")

__global__ void __launch_bounds__(256) k_conv_tc(const float* __restrict__ cw,
                                                 const float* __restrict__ cb){
    extern __shared__ char smem[];
    uint32_t sbase = smem_u32(smem);
    float* red = (float*)(smem + CV_RED);
    int t = threadIdx.x;
    int wid = t >> 5, lane = t & 31;
    int tile = blockIdx.x, b = blockIdx.y;
    int p0 = tile*CTM;

    if (t < 32) red[t] = 0.f;

    for (int idx = t; idx < 9*32*32; idx += 256){
        int qd = idx >> 10, rem = idx & 1023;
        int o = rem >> 5, i = rem & 31;
        float v = (o < NC && i < NC) ? cw[(o*NC + i)*9 + qd] : 0.f;
        uint32_t hr;
        asm("cvt.rn.bf16x2.f32 %0, %1, %2;" : "=r"(hr) : "f"(0.f), "f"(v));
        float hi_f = __uint_as_float(hr << 16);
        float lo_f = v - hi_f;
        uint32_t lr;
        asm("cvt.rn.bf16x2.f32 %0, %1, %2;" : "=r"(lr) : "f"(0.f), "f"(lo_f));
        uint32_t off = (uint32_t)qd*32*XSTR + (uint32_t)o*XSTR + (uint32_t)i*2;
        *(uint16_t*)(smem + CV_WH + off) = (uint16_t)(hr & 0xFFFF);
        *(uint16_t*)(smem + CV_WL + off) = (uint16_t)(lr & 0xFFFF);
    }

    const float* hb_ptr = g_h + (size_t)b*NC*NP;
    for (int idx = t; idx < CROWS*32; idx += 256){
        int c = idx / CROWS, row = idx % CROWS;
        int pp = p0 - 18 + row;
        float v = 0.f;
        if (c < NC && pp >= 0 && pp < PPTOT){
            int xx = pp / PADY, yy = pp % PADY;
            if (yy >= 1 && yy <= 15) v = hb_ptr[(size_t)c*NP + xx*SYv + (yy-1)];
        }
        uint32_t r2;
        asm("cvt.rn.bf16x2.f32 %0, %1, %2;" : "=r"(r2) : "f"(0.f), "f"(v));
        *(uint16_t*)(smem + CV_XS + (uint32_t)row*XSTR + (uint32_t)c*2) = (uint16_t)(r2 & 0xFFFF);
    }
    __syncthreads();

    float acc[4][4];
    #pragma unroll
    for (int nj = 0; nj < 4; nj++)
        #pragma unroll
        for (int qd = 0; qd < 4; qd++) acc[nj][qd] = 0.f;

    uint32_t a_base = sbase + CV_XS + (uint32_t)(18 + wid*16 + (lane & 15))*XSTR + ((lane >> 4)*16);
    uint32_t b_row = (uint32_t)(((lane >> 4) & 1)*8 + (lane & 7));
    uint32_t b_koff = ((lane >> 3) & 1)*16;

    #pragma unroll
    for (int qd = 0; qd < 9; qd++){
        int off = (qd/3 - 1)*PADY + (qd%3 - 1);
        uint32_t wq = (uint32_t)qd*32*XSTR;
        #pragma unroll
        for (int ks = 0; ks < 2; ks++){
            uint32_t Af[4], Bh[2][4], Bl[2][4];
            LDSM4(Af, a_base + off*XSTR + ks*32);
            #pragma unroll
            for (int ni = 0; ni < 2; ni++){
                uint32_t bd = sbase + CV_WH + wq + (b_row + ni*16)*XSTR + ks*32 + b_koff;
                LDSM4(Bh[ni], bd);
                LDSM4(Bl[ni], bd + (CV_WL - CV_WH));
            }
            #pragma unroll
            for (int nj = 0; nj < 4; nj++){
                uint32_t* BH = Bh[nj>>1] + 2*(nj&1);
                uint32_t* BL = Bl[nj>>1] + 2*(nj&1);
                MMA16816(acc[nj], Af, BH[0], BH[1]);
                MMA16816(acc[nj], Af, BL[0], BL[1]);
            }
        }
    }

    int g = lane >> 2, tig = lane & 3;
    int r0 = p0 + wid*16 + g;
    int r1 = r0 + 8;
    int y0 = r0 % PADY, y1 = r1 % PADY;
    bool v0 = (r0 < PPTOT) && (y0 >= 1) && (y0 <= 15);
    bool v1 = (r1 < PPTOT) && (y1 >= 1) && (y1 <= 15);

    #pragma unroll
    for (int nj = 0; nj < 4; nj++){
        int c0 = nj*8 + 2*tig, c1 = c0 + 1;
        float bc0 = (c0 < NC) ? cb[c0] : 0.f;
        float bc1 = (c1 < NC) ? cb[c1] : 0.f;
        float s0 = v0 ? fmaxf(acc[nj][0] + bc0, 0.f) : 0.f;
        float s1 = v0 ? fmaxf(acc[nj][1] + bc1, 0.f) : 0.f;
        float s2 = v1 ? fmaxf(acc[nj][2] + bc0, 0.f) : 0.f;
        float s3 = v1 ? fmaxf(acc[nj][3] + bc1, 0.f) : 0.f;
        float t0 = s0 + s2, t1 = s1 + s3;
        #pragma unroll
        for (int o = 16; o >= 4; o >>= 1){
            t0 += __shfl_down_sync(0xFFFFFFFFu, t0, o);
            t1 += __shfl_down_sync(0xFFFFFFFFu, t1, o);
        }
        if (lane < 4){
            if (c0 < NC) atomicAdd(&red[c0], t0);
            if (c1 < NC) atomicAdd(&red[c1], t1);
        }
    }
    __syncthreads();
    if (t < NC) atomicAdd(&g_ap[b*NC + t], red[t]);
}

__global__ void k_att(const float* __restrict__ fw, const float* __restrict__ fb){
    int b = blockIdx.x*blockDim.x + threadIdx.x;
    if (b < NB){
        float s = fb[0];
        #pragma unroll
        for (int c = 0; c < NC; c++) s = fmaf(g_ap[b*NC+c]*(1.0f/NP), fw[c], s);
        g_att[b] = 1.0f/(1.0f + expf(-s));
    }
}

// =====================================================================
// GEMM1: tall tile M=256 x N=64, W fp32 read once + in-kernel convert.
// A fp16 via 3-stage cp.async (wait_group 1); B fp32 reg-prefetch + cvt, 2-stage.
// Grid (44, 13). 8 warps: warp grid 4(M) x 2(N), warp tile 64x32.
// =====================================================================
#define G2_ASTAGE 20480          // 256 rows * 80
#define G2_BOFF   (3*G2_ASTAGE)  // 61440
#define G2_BSTAGE 5120           // 64 rows * 80
#define G2_SMEM   (3*G2_ASTAGE + 2*G2_BSTAGE)   // 71680

__global__ void __launch_bounds__(256, 2) k_gemm1_mma(const float* __restrict__ W){
    extern __shared__ char smem[];
    uint32_t sbase = smem_u32(smem);
    int t = threadIdx.x;
    int wid = t >> 5, lane = t & 31;
    int n0 = blockIdx.x*64, z = blockIdx.y;
    int c0 = (z*NCH32)/SPLITK1, c1 = ((z+1)*NCH32)/SPLITK1;

    int m_w = (wid & 3)*64;
    int n_w = (wid >> 2)*32;

    const __half* Asrc = g_Ah + (size_t)t*KPADH;
    uint32_t a_dst = (uint32_t)t*80;
    int rb = t >> 2, seg = t & 3;
    int brow = n0 + rb;
    const float* Bsrc = W + (size_t)((brow < NH1) ? brow : (NH1-1))*KTOT + seg*8;
    uint32_t b_dst = G2_BOFF + (uint32_t)rb*80 + (uint32_t)seg*16;

    float acc[4][4][4];
    #pragma unroll
    for (int mi = 0; mi < 4; mi++)
        #pragma unroll
        for (int nj = 0; nj < 4; nj++)
            #pragma unroll
            for (int q = 0; q < 4; q++) acc[mi][nj][q] = 0.f;

    // preload A(c0), A(c0+1); B(c0)
    {
        uint32_t d = sbase + a_dst;
        const char* sp = (const char*)(Asrc + c0*32);
        CP16(d, sp); CP16(d+16, sp+16); CP16(d+32, sp+32); CP16(d+48, sp+48);
        CP_COMMIT();
        if (c0 + 1 < c1){
            uint32_t d1 = sbase + G2_ASTAGE + a_dst;
            const char* sp1 = (const char*)(Asrc + (c0+1)*32);
            CP16(d1, sp1); CP16(d1+16, sp1+16); CP16(d1+32, sp1+32); CP16(d1+48, sp1+48);
            CP_COMMIT();
        }
        float2 vb[4];
        int kbase = c0*32 + seg*8;
        #pragma unroll
        for (int j = 0; j < 4; j++){
            int kg = kbase + 2*j;
            vb[j] = (kg < KTOT) ? *(const float2*)(Bsrc + c0*32 + 2*j) : make_float2(0.f, 0.f);
        }
        __half2 p0 = __floats2half2_rn(vb[0].x, vb[0].y);
        __half2 p1 = __floats2half2_rn(vb[1].x, vb[1].y);
        __half2 p2 = __floats2half2_rn(vb[2].x, vb[2].y);
        __half2 p3 = __floats2half2_rn(vb[3].x, vb[3].y);
        uint4 u = make_uint4(*(uint32_t*)&p0, *(uint32_t*)&p1, *(uint32_t*)&p2, *(uint32_t*)&p3);
        *(uint4*)(smem + b_dst) = u;
    }

    uint32_t a_row = (uint32_t)(m_w + (lane & 15));
    uint32_t a_koff = ((lane >> 4) & 1)*16;
    uint32_t b_row = (uint32_t)(n_w + ((lane >> 4) & 1)*8 + (lane & 7));
    uint32_t b_koff = ((lane >> 3) & 1)*16;

    for (int c = c0; c < c1; c++){
        int rel = c - c0;
        uint32_t sa = sbase + (uint32_t)(rel % 3)*G2_ASTAGE;
        uint32_t sbB = sbase + (uint32_t)(rel & 1)*G2_BSTAGE;
        bool more = (c + 1 < c1);

        CP_WAIT1();          // A(c) complete (A(c+1) may remain pending)
        __syncthreads();     // publish A(c) + B(c)

        if (c + 2 < c1){
            uint32_t d = sbase + (uint32_t)((rel + 2) % 3)*G2_ASTAGE + a_dst;
            const char* sp = (const char*)(Asrc + (c+2)*32);
            CP16(d, sp); CP16(d+16, sp+16); CP16(d+32, sp+32); CP16(d+48, sp+48);
            CP_COMMIT();
        }
        float2 vb[4];
        if (more){
            #pragma unroll
            for (int j = 0; j < 4; j++){
                int kg = (c+1)*32 + seg*8 + 2*j;
                vb[j] = (kg < KTOT) ? *(const float2*)(Bsrc + (c+1)*32 + 2*j) : make_float2(0.f, 0.f);
            }
        }

        #pragma unroll
        for (int ks = 0; ks < 2; ks++){
            uint32_t ksb = ks*32;
            uint32_t Ah[4][4], Bh[2][4];
            #pragma unroll
            for (int mi = 0; mi < 4; mi++){
                uint32_t ad = sa + (a_row + mi*16)*80 + ksb + a_koff;
                LDSM4(Ah[mi], ad);
            }
            #pragma unroll
            for (int ni = 0; ni < 2; ni++){
                uint32_t bd = sbB + G2_BOFF + (b_row + ni*16)*80 + ksb + b_koff;
                LDSM4(Bh[ni], bd);
            }
            #pragma unroll
            for (int mi = 0; mi < 4; mi++)
                #pragma unroll
                for (int nj = 0; nj < 4; nj++){
                    uint32_t* BH = Bh[nj>>1] + 2*(nj&1);
                    MMAF16(acc[mi][nj], Ah[mi], BH[0], BH[1]);
                }
        }

        if (more){
            __half2 p0 = __floats2half2_rn(vb[0].x, vb[0].y);
            __half2 p1 = __floats2half2_rn(vb[1].x, vb[1].y);
            __half2 p2 = __floats2half2_rn(vb[2].x, vb[2].y);
            __half2 p3 = __floats2half2_rn(vb[3].x, vb[3].y);
            uint4 u = make_uint4(*(uint32_t*)&p0, *(uint32_t*)&p1, *(uint32_t*)&p2, *(uint32_t*)&p3);
            *(uint4*)(smem + ((rel+1) & 1)*G2_BSTAGE + b_dst) = u;
        }
    }

    int g = lane >> 2, tig = lane & 3;
    #pragma unroll
    for (int mi = 0; mi < 4; mi++){
        int mrow = m_w + mi*16 + g;
        #pragma unroll
        for (int nj = 0; nj < 4; nj++){
            int ncol = n0 + n_w + nj*8 + 2*tig;
            if (ncol < NH1){
                float* d0 = g_Cp + ((size_t)z*NB + mrow)*NH1 + ncol;
                *(float2*)d0 = make_float2(acc[mi][nj][0], acc[mi][nj][1]);
                float* d1 = d0 + (size_t)8*NH1;
                *(float2*)d1 = make_float2(acc[mi][nj][2], acc[mi][nj][3]);
            }
        }
    }
}

__global__ void k_comb1(const float* __restrict__ b1){
    int i = blockIdx.x*256 + threadIdx.x;
    if (i >= NB*NH1) return;
    int b = i/NH1, j = i - b*NH1;
    float v = 0.f;
    #pragma unroll
    for (int z = 0; z < SPLITK1; z++) v += g_Cp[(size_t)z*NB*NH1 + i];
    v = v * g_att[b] + b1[j];
    g_C[i] = (v > 0.f) ? v : 0.01f*v;
}

// ---------------- small split-K tiled SGEMM for layer 2 ----------------
template<int SPLITK>
__global__ void __launch_bounds__(256) k_gemm(const float* __restrict__ Bmat, int N, int K){
    const float* A = g_C;
    int n0 = blockIdx.x*64, m0 = blockIdx.y*64, z = blockIdx.z;
    int ck = (K + SPLITK - 1)/SPLITK;
    int k0 = z*ck, kend = min(K, k0 + ck);
    __shared__ float As[64][17], Bs[64][17];
    float acc[4][4];
    #pragma unroll
    for (int mi = 0; mi < 4; mi++)
        #pragma unroll
        for (int ni = 0; ni < 4; ni++) acc[mi][ni] = 0.f;
    int tr = threadIdx.x >> 4, tc = threadIdx.x & 15;
    for (int kt = k0; kt < kend; kt += 16){
        #pragma unroll
        for (int l = 0; l < 4; l++){
            int i = threadIdx.x + l*256;
            int rr = i >> 4, cc = i & 15;
            int k = kt + cc;
            As[rr][cc] = (k < kend) ? A[(size_t)(m0+rr)*K + k] : 0.f;
            int j = n0 + rr;
            Bs[rr][cc] = (k < kend && j < N) ? Bmat[(size_t)j*K + k] : 0.f;
        }
        __syncthreads();
        #pragma unroll
        for (int kk = 0; kk < 16; kk++){
            float a[4], bb[4];
            #pragma unroll
            for (int mi = 0; mi < 4; mi++) a[mi]  = As[tr*4+mi][kk];
            #pragma unroll
            for (int ni = 0; ni < 4; ni++) bb[ni] = Bs[tc*4+ni][kk];
            #pragma unroll
            for (int mi = 0; mi < 4; mi++)
                #pragma unroll
                for (int ni = 0; ni < 4; ni++) acc[mi][ni] = fmaf(a[mi], bb[ni], acc[mi][ni]);
        }
        __syncthreads();
    }
    #pragma unroll
    for (int mi = 0; mi < 4; mi++)
        #pragma unroll
        for (int ni = 0; ni < 4; ni++){
            int m = m0 + tr*4 + mi, n = n0 + tc*4 + ni;
            if (n < N) g_Cp[(size_t)z*NB*N + (size_t)m*N + n] = acc[mi][ni];
        }
}

__global__ void k_comb2(const float* __restrict__ b2){
    int i = blockIdx.x*256 + threadIdx.x;
    if (i >= NB*NO) return;
    int j = i % NO;
    float v = b2[j];
    #pragma unroll
    for (int z = 0; z < 8; z++) v += g_Cp[(size_t)z*NB*NO + i];
    g_x1[i] = v;
}

__global__ void k_head(const float* __restrict__ x, const float* __restrict__ rw,
                       const float* __restrict__ rb, float* __restrict__ out){
    int b = blockIdx.x, t = threadIdx.x;
    float x0 = (x[(size_t)b*SXv*(SYv+1) + t*(SYv+1) + SYv] - 400.0f)*0.01f;
    float v = g_x1[b*NO + t]*rw[2*t] + x0*rw[2*t+1];
    __shared__ float s[128];
    s[t] = v; __syncthreads();
    for (int o = 64; o > 0; o >>= 1){ if (t < o) s[t] += s[t+o]; __syncthreads(); }
    if (t == 0) out[b] = s[0] + rb[0];
}

// ---------------- launch ----------------
extern "C" void kernel_launch(void* const* d_in, const int* in_sizes, int n_in,
                              void* d_out, int out_size){
    const float* x      = (const float*)d_in[0];
    const float* p_w    = (const float*)d_in[1];
    const float* p_b    = (const float*)d_in[2];
    const float* sc0_w1 = (const float*)d_in[3];
    const float* sc0_w2 = (const float*)d_in[4];
    const float* sc1_w1 = (const float*)d_in[5];
    const float* sc1_w2 = (const float*)d_in[6];
    const float* mlp0_w1= (const float*)d_in[7];
    const float* mlp0_b1= (const float*)d_in[8];
    const float* mlp0_w2= (const float*)d_in[9];
    const float* mlp0_b2= (const float*)d_in[10];
    const float* mlp1_w1= (const float*)d_in[11];
    const float* mlp1_b1= (const float*)d_in[12];
    const float* mlp1_w2= (const float*)d_in[13];
    const float* mlp1_b2= (const float*)d_in[14];
    const float* w0_w   = (const float*)d_in[15];
    const float* w0_b   = (const float*)d_in[16];
    const float* w1_w   = (const float*)d_in[17];
    const float* w1_b   = (const float*)d_in[18];
    const float* sa_cw  = (const float*)d_in[19];
    const float* sa_cb  = (const float*)d_in[20];
    const float* sa_fw  = (const float*)d_in[21];
    const float* sa_fb  = (const float*)d_in[22];
    const float* o1_w1  = (const float*)d_in[23];
    const float* o1_b1  = (const float*)d_in[24];
    const float* o1_w2  = (const float*)d_in[25];
    const float* o1_b2  = (const float*)d_in[26];
    const float* reg2_w = (const float*)d_in[27];
    const float* reg2_b = (const float*)d_in[28];
    float* out = (float*)d_out;

    cudaFuncSetAttribute(k_gemm1_mma, cudaFuncAttributeMaxDynamicSharedMemorySize, G2_SMEM);
    cudaFuncSetAttribute(k_conv_tc,   cudaFuncAttributeMaxDynamicSharedMemorySize, CV_SMEM);
    cudaFuncSetAttribute(k_idft,      cudaFuncAttributeMaxDynamicSharedMemorySize, ID_SMEM);

    k_twiddle<<<28, 256>>>();

    // Fourier block 0 (mix merged into idft)
    k_fdft<<<NB*NC, 256>>>(x, p_w, p_b, 1);
    k_idft<<<NB*NC, 256, ID_SMEM>>>(sc0_w1, sc0_w2);
    k_fuse<<<dim3((NP+255)/256, NB), 256>>>(mlp0_w1, mlp0_b1, mlp0_w2, mlp0_b2, w0_w, w0_b, 0);

    // Fourier block 1 (fuse writes fp16 A directly)
    k_fdft<<<NB*NC, 256>>>(x, p_w, p_b, 0);
    k_idft<<<NB*NC, 256, ID_SMEM>>>(sc1_w1, sc1_w2);
    k_fuse<<<dim3((NP+255)/256, NB), 256>>>(mlp1_w1, mlp1_b1, mlp1_w2, mlp1_b2, w1_w, w1_b, 1);

    // ---- fork: spatial attention on side stream ----
    cudaEventRecord(g_sp.eFuse, 0);
    cudaStreamWaitEvent(g_sp.s2, g_sp.eFuse, 0);
    k_conv_tc<<<dim3(NTILE, NB), 256, CV_SMEM, g_sp.s2>>>(sa_cw, sa_cb);
    k_att<<<1, 256, 0, g_sp.s2>>>(sa_fw, sa_fb);
    cudaEventRecord(g_sp.eAtt, g_sp.s2);

    // main stream: big GEMM (W fp32 read directly, converted in-kernel)
    k_gemm1_mma<<<dim3(44, SPLITK1), 256, G2_SMEM>>>(o1_w1);

    cudaStreamWaitEvent(0, g_sp.eAtt, 0);
    k_comb1<<<(NB*NH1+255)/256, 256>>>(o1_b1);
    k_gemm<8><<<dim3(2, 4, 8), 256>>>(o1_w2, NO, 2808);
    k_comb2<<<(NB*NO+255)/256, 256>>>(o1_b2);
    k_head<<<NB, 128>>>(x, reg2_w, reg2_b, out);
}

// round 16
// speedup vs baseline: 1.0160x; 1.0160x over previous
#include <cuda_runtime.h>
#include <cuda_fp16.h>
#include <math.h>
#include <stdint.h>

#define NB 256
#define NC 26
#define SXv 179
#define SYv 15
#define NP (SXv*SYv)          // 2685
#define MM 7
#define NMODE (14*MM)         // 98
#define KTOT (NC*NP)          // 69810
#define KPADH 69824           // padded to /64 (16B-aligned fp16 rows)
#define NH1 2808
#define NO 128
#define NCH32 2182            // ceil(69810/32)
#define SPLITK1 13

// ---------------- device scratch ----------------
__device__ float  g_h [NB*NC*NP];
__device__ float  g_t2[NB*NC*NP];
__device__ float2 g_F [NB*NC*NMODE];
__device__ float2 g_G [NB*NC*NMODE];
__device__ float2 g_txf[14*SXv];
__device__ float2 g_txi[14*SXv];
__device__ float2 g_twyf[MM*SYv];
__device__ float2 g_twy2[MM*SYv];
__device__ float  g_ap [NB*NC];
__device__ float  g_att[NB];
__device__ float  g_Cp [SPLITK1*NB*NH1];
__device__ float  g_C  [NB*NH1];
__device__ float  g_x1 [NB*NO];
__device__ __half g_Ah[(size_t)NB*KPADH];    // 35.8 MB

// ---------------- host-side stream/event pack ----------------
struct SidePack {
    cudaStream_t s2;
    cudaEvent_t eFuse, eAtt;
    SidePack(){
        cudaStreamCreateWithFlags(&s2, cudaStreamNonBlocking);
        cudaEventCreateWithFlags(&eFuse, cudaEventDisableTiming);
        cudaEventCreateWithFlags(&eAtt,  cudaEventDisableTiming);
    }
};
static SidePack g_sp;

__device__ __forceinline__ float gelu_f(float x){
    return 0.5f*x*(1.0f + erff(x*0.70710678118654752f));
}

__device__ __forceinline__ uint32_t smem_u32(const void* p){
    uint32_t a;
    asm("{ .reg .u64 t; cvta.to.shared.u64 t, %1; cvt.u32.u64 %0, t; }" : "=r"(a) : "l"(p));
    return a;
}

__device__ __forceinline__ void block_reduce2(float s, float q, float* shm,
                                              float& osum, float& osq){
    int t = threadIdx.x, lane = t & 31, wid = t >> 5;
    #pragma unroll
    for (int o = 16; o > 0; o >>= 1){
        s += __shfl_down_sync(0xFFFFFFFFu, s, o);
        q += __shfl_down_sync(0xFFFFFFFFu, q, o);
    }
    if (lane == 0){ shm[wid] = s; shm[8 + wid] = q; }
    __syncthreads();
    if (t == 0){
        float ss = 0.f, qq = 0.f;
        #pragma unroll
        for (int i = 0; i < 8; i++){ ss += shm[i]; qq += shm[8 + i]; }
        shm[16] = ss; shm[17] = qq;
    }
    __syncthreads();
    osum = shm[16]; osq = shm[17];
}

// ---------------- twiddle tables + g_ap zero + g_Ah padding ----------------
__global__ void k_twiddle(){
    int i = blockIdx.x*blockDim.x + threadIdx.x;
    if (i < 14*SXv){
        int k1i = i/SXv, xx = i%SXv;
        int keff = (k1i < 7) ? k1i : (14 - k1i);
        float sn, cs;
        sincospif(2.0f*(float)(keff*xx)/179.0f, &sn, &cs);
        g_txf[i] = make_float2(cs, (k1i < 7) ? -sn : sn);
        g_txi[i] = make_float2(cs, (k1i < 7) ? sn : -sn);
    }
    if (i < MM*SYv){
        int k = i/SYv, y = i%SYv;
        float sn, cs;
        sincospif(2.0f*(float)(k*y)/15.0f, &sn, &cs);
        g_twyf[i] = make_float2(cs, -sn);
        g_twy2[i] = make_float2(2.f*cs, 2.f*sn);
    }
    if (i < NB*NC) g_ap[i] = 0.f;
    if (i < NB*(KPADH - KTOT)){
        int row = i/(KPADH - KTOT), col = KTOT + i%(KPADH - KTOT);
        g_Ah[(size_t)row*KPADH + col] = __float2half(0.f);
    }
}

// ---------------- fused lift + instance-norm + forward truncated DFT ----------------
__global__ void __launch_bounds__(256) k_fdft(const float* __restrict__ x,
                                              const float* __restrict__ pw,
                                              const float* __restrict__ pb,
                                              int first){
    int bc = blockIdx.x;
    __shared__ float  sp[NP];
    __shared__ float2 Ys[SXv*MM];
    __shared__ float2 Pp[2*NMODE];
    __shared__ float  red[18];
    int t = threadIdx.x;

    float s = 0.f, q = 0.f;
    if (first){
        int b = bc / NC, w = bc % NC;
        float w0 = pw[w*3+0], w1 = pw[w*3+1], w2 = pw[w*3+2], bb = pb[w];
        const float* xb = x + (size_t)b*SXv*(SYv+1);
        float* outp = g_h + (size_t)bc*NP;
        for (int p = t; p < NP; p += 256){
            int xi = p/SYv, yi = p%SYv;
            float u = xb[xi*(SYv+1) + yi];
            float v = u*w0 + ((float)xi*(1.0f/178.0f))*w1 + ((float)yi*(1.0f/14.0f))*w2 + bb;
            outp[p] = v;
            sp[p] = v;
            s += v; q += v*v;
        }
    } else {
        const float* src = g_h + (size_t)bc*NP;
        for (int p = t; p < NP; p += 256){
            float v = src[p];
            sp[p] = v;
            s += v; q += v*v;
        }
    }
    __syncthreads();
    float sum, sq;
    block_reduce2(s, q, red, sum, sq);
    float mu  = sum * (1.0f/NP);
    float var = sq * (1.0f/NP) - mu*mu;
    float inv = rsqrtf(var + 1e-5f);
    for (int p = t; p < NP; p += 256) sp[p] = (sp[p] - mu)*inv;
    __syncthreads();

    for (int idx = t; idx < SXv*MM; idx += 256){
        int xx = idx/MM, k2 = idx%MM;
        float re = 0.f, im = 0.f;
        #pragma unroll
        for (int y = 0; y < SYv; y++){
            float2 tw = g_twyf[k2*SYv + y];
            float v = sp[xx*SYv + y];
            re = fmaf(v, tw.x, re);
            im = fmaf(v, tw.y, im);
        }
        Ys[idx] = make_float2(re, im);
    }
    __syncthreads();

    if (t < 2*NMODE){
        int mode = t >> 1, half = t & 1;
        int k1i = mode/MM, k2 = mode%MM;
        const float2* tw = g_txf + k1i*SXv;
        int xa = half ? 90 : 0, xbnd = half ? SXv : 90;
        float re = 0.f, im = 0.f;
        #pragma unroll 3
        for (int xx = xa; xx < xbnd; xx++){
            float2 u = tw[xx];
            float2 y = Ys[xx*MM + k2];
            re += y.x*u.x - y.y*u.y;
            im += y.x*u.y + y.y*u.x;
        }
        Pp[t] = make_float2(re, im);
    }
    __syncthreads();
    if (t < NMODE){
        float2 a = Pp[2*t], b2 = Pp[2*t+1];
        g_F[(size_t)bc*NMODE + t] = make_float2(a.x + b2.x, a.y + b2.y);
    }
}

// ---------------- complex channel mix (g_F -> g_G) ----------------
__global__ void k_mix(const float* __restrict__ w1, const float* __restrict__ w2){
    int b = blockIdx.x, seg = blockIdx.y;
    __shared__ float2 Fs[NC*NMODE];
    for (int i = threadIdx.x; i < NC*NMODE; i += 256)
        Fs[i] = g_F[(size_t)b*NC*NMODE + i];
    __syncthreads();
    int s0 = (seg*NC*NMODE) >> 2, s1 = ((seg+1)*NC*NMODE) >> 2;
    for (int oi = s0 + threadIdx.x; oi < s1; oi += 256){
        int o = oi/NMODE, mode = oi%NMODE;
        int k1i = mode/MM, k2 = mode%MM;
        const float2* wp;
        if (k1i < 7) wp = (const float2*)w1 + ((size_t)(o*MM + k1i)*MM + k2);
        else         wp = (const float2*)w2 + ((size_t)(o*MM + (k1i-7))*MM + k2);
        float re = 0.f, im = 0.f;
        #pragma unroll 2
        for (int i = 0; i < NC; i++){
            float2 f = Fs[i*NMODE + mode];
            float2 w = *wp;
            re += f.x*w.x - f.y*w.y;
            im += f.x*w.y + f.y*w.x;
            wp += NC*MM*MM;
        }
        g_G[(size_t)b*NC*NMODE + oi] = make_float2(re, im);
    }
}

// ---------------- fused inverse truncated DFT + instance norm ----------------
__global__ void __launch_bounds__(256) k_idft(){
    int bc = blockIdx.x;
    __shared__ float2 Gs[NMODE];
    __shared__ float2 Ss[SXv*MM];
    __shared__ float  pl[NP];
    __shared__ float  red[18];
    int t = threadIdx.x;
    for (int i = t; i < NMODE; i += 256){
        float2 g = g_G[(size_t)bc*NMODE + i];
        Gs[i] = make_float2(g.x*(1.0f/(179.0f*15.0f)), g.y*(1.0f/(179.0f*15.0f)));
    }
    __syncthreads();
    for (int idx = t; idx < SXv*MM; idx += 256){
        int n1 = idx/MM, k2 = idx%MM;
        float re = 0.f, im = 0.f;
        #pragma unroll
        for (int k1i = 0; k1i < 14; k1i++){
            float2 g = Gs[k1i*MM + k2];
            float2 u = g_txi[k1i*SXv + n1];
            re += g.x*u.x - g.y*u.y;
            im += g.x*u.y + g.y*u.x;
        }
        Ss[idx] = make_float2(re, im);
    }
    __syncthreads();
    float s = 0.f, q = 0.f;
    for (int p = t; p < NP; p += 256){
        int n1 = p/SYv, n2 = p%SYv;
        float val = Ss[n1*MM].x;
        #pragma unroll
        for (int k2 = 1; k2 < MM; k2++){
            float2 sv = Ss[n1*MM + k2];
            float2 tw = g_twy2[k2*SYv + n2];
            val += sv.x*tw.x - sv.y*tw.y;
        }
        pl[p] = val;
        s += val; q += val*val;
    }
    __syncthreads();
    float sum, sq;
    block_reduce2(s, q, red, sum, sq);
    float mu  = sum * (1.0f/NP);
    float var = sq * (1.0f/NP) - mu*mu;
    float inv = rsqrtf(var + 1e-5f);
    float* d = g_t2 + (size_t)bc*NP;
    for (int p = t; p < NP; p += 256) d[p] = (pl[p] - mu)*inv;
}

// ---------------- fused: h = gelu( mlp(g_t2) + c1(h) ) ----------------
// writeAh=0: write fp32 g_h.  writeAh=1: write ONLY fp16 g_Ah (consumers: GEMM, conv).
__global__ void __launch_bounds__(256) k_fuse(
        const float* __restrict__ w1, const float* __restrict__ b1,
        const float* __restrict__ w2, const float* __restrict__ b2,
        const float* __restrict__ wr, const float* __restrict__ br,
        int writeAh){
    __shared__ float sw1[NC*NC], sw2[NC*NC], swr[NC*NC], sb1[NC], sb2[NC], sbr[NC];
    int t = threadIdx.x;
    for (int i = t; i < NC*NC; i += 256){ sw1[i] = w1[i]; sw2[i] = w2[i]; swr[i] = wr[i]; }
    if (t < NC){ sb1[t] = b1[t]; sb2[t] = b2[t]; sbr[t] = br[t]; }
    __syncthreads();
    int p = blockIdx.x*256 + t;
    if (p >= NP) return;
    int b = blockIdx.y;
    size_t base = (size_t)b*NC*NP + p;
    float xin[NC], tm[NC];
    #pragma unroll
    for (int i = 0; i < NC; i++) xin[i] = g_t2[base + (size_t)i*NP];
    #pragma unroll
    for (int o = 0; o < NC; o++){
        float a = sb1[o];
        #pragma unroll
        for (int i = 0; i < NC; i++) a = fmaf(xin[i], sw1[o*NC+i], a);
        tm[o] = gelu_f(a);
    }
    float hin[NC];
    #pragma unroll
    for (int i = 0; i < NC; i++) hin[i] = g_h[base + (size_t)i*NP];
    __half* ahp = g_Ah + (size_t)b*KPADH + p;
    #pragma unroll
    for (int o = 0; o < NC; o++){
        float a = sb2[o] + sbr[o];
        #pragma unroll
        for (int i = 0; i < NC; i++) a = fmaf(tm[i],  sw2[o*NC+i], a);
        #pragma unroll
        for (int i = 0; i < NC; i++) a = fmaf(hin[i], swr[o*NC+i], a);
        float gv = gelu_f(a);
        if (writeAh) ahp[(size_t)o*NP] = __float2half(gv);
        else         g_h[base + (size_t)o*NP] = gv;
    }
}

// =====================================================================
// Tensor-core conv3x3 + relu + pooling (fused) — reads fp16 g_Ah
// =====================================================================
#define PADY 17
#define PPTOT (SXv*PADY)
#define CTM 128
#define NTILE 24
#define CROWS (CTM + 36)
#define XSTR 80
#define CV_XS 0
#define CV_WH (CROWS*XSTR)
#define CV_WL (CV_WH + 9*32*XSTR)
#define CV_RED (CV_WL + 9*32*XSTR)
#define CV_SMEM (CV_RED + 128)

#define LDSM4(R, ADDR) \
    asm volatile("ldmatrix.sync.aligned.m8n8.x4.shared.b16 {%0,%1,%2,%3}, [%4];" \
        : "=r"((R)[0]), "=r"((R)[1]), "=r"((R)[2]), "=r"((R)[3]) : "r"(ADDR))

#define MMA16816(D, A, B0, B1) \
    asm volatile("mma.sync.aligned.m16n8k16.row.col.f32.bf16.bf16.f32 " \
        "{%0,%1,%2,%3}, {%4,%5,%6,%7}, {%8,%9}, {%0,%1,%2,%3};" \
        : "+f"((D)[0]), "+f"((D)[1]), "+f"((D)[2]), "+f"((D)[3]) \
        : "r"((A)[0]), "r"((A)[1]), "r"((A)[2]), "r"((A)[3]), "r"(B0), "r"(B1))

#define MMAF16(D, A, B0, B1) \
    asm volatile("mma.sync.aligned.m16n8k16.row.col.f32.f16.f16.f32 " \
        "{%0,%1,%2,%3}, {%4,%5,%6,%7}, {%8,%9}, {%0,%1,%2,%3};" \
        : "+f"((D)[0]), "+f"((D)[1]), "+f"((D)[2]), "+f"((D)[3]) \
        : "r"((A)[0]), "r"((A)[1]), "r"((A)[2]), "r"((A)[3]), "r"(B0), "r"(B1))

#define CP16(dst, src) asm volatile("cp.async.cg.shared.global [%0], [%1], 16;" :: "r"(dst), "l"(src) : "memory")
#define CP_COMMIT() asm volatile("cp.async.commit_group;" ::: "memory")
#define CP_WAIT0()  asm volatile("cp.async.wait_group 0;" ::: "memory")
#define CP_WAIT1()  asm volatile("cp.async.wait_group 1;" ::: "memory")

__global__ void __launch_bounds__(256) k_conv_tc(const float* __restrict__ cw,
                                                 const float* __restrict__ cb){
    extern __shared__ char smem[];
    uint32_t sbase = smem_u32(smem);
    float* red = (float*)(smem + CV_RED);
    int t = threadIdx.x;
    int wid = t >> 5, lane = t & 31;
    int tile = blockIdx.x, b = blockIdx.y;
    int p0 = tile*CTM;

    if (t < 32) red[t] = 0.f;

    for (int idx = t; idx < 9*32*32; idx += 256){
        int qd = idx >> 10, rem = idx & 1023;
        int o = rem >> 5, i = rem & 31;
        float v = (o < NC && i < NC) ? cw[(o*NC + i)*9 + qd] : 0.f;
        uint32_t hr;
        asm("cvt.rn.bf16x2.f32 %0, %1, %2;" : "=r"(hr) : "f"(0.f), "f"(v));
        float hi_f = __uint_as_float(hr << 16);
        float lo_f = v - hi_f;
        uint32_t lr;
        asm("cvt.rn.bf16x2.f32 %0, %1, %2;" : "=r"(lr) : "f"(0.f), "f"(lo_f));
        uint32_t off = (uint32_t)qd*32*XSTR + (uint32_t)o*XSTR + (uint32_t)i*2;
        *(uint16_t*)(smem + CV_WH + off) = (uint16_t)(hr & 0xFFFF);
        *(uint16_t*)(smem + CV_WL + off) = (uint16_t)(lr & 0xFFFF);
    }

    const __half* hb_ptr = g_Ah + (size_t)b*KPADH;
    for (int idx = t; idx < CROWS*32; idx += 256){
        int c = idx / CROWS, row = idx % CROWS;
        int pp = p0 - 18 + row;
        float v = 0.f;
        if (c < NC && pp >= 0 && pp < PPTOT){
            int xx = pp / PADY, yy = pp % PADY;
            if (yy >= 1 && yy <= 15) v = __half2float(hb_ptr[(size_t)c*NP + xx*SYv + (yy-1)]);
        }
        uint32_t r2;
        asm("cvt.rn.bf16x2.f32 %0, %1, %2;" : "=r"(r2) : "f"(0.f), "f"(v));
        *(uint16_t*)(smem + CV_XS + (uint32_t)row*XSTR + (uint32_t)c*2) = (uint16_t)(r2 & 0xFFFF);
    }
    __syncthreads();

    float acc[4][4];
    #pragma unroll
    for (int nj = 0; nj < 4; nj++)
        #pragma unroll
        for (int qd = 0; qd < 4; qd++) acc[nj][qd] = 0.f;

    uint32_t a_base = sbase + CV_XS + (uint32_t)(18 + wid*16 + (lane & 15))*XSTR + ((lane >> 4)*16);
    uint32_t b_row = (uint32_t)(((lane >> 4) & 1)*8 + (lane & 7));
    uint32_t b_koff = ((lane >> 3) & 1)*16;

    #pragma unroll
    for (int qd = 0; qd < 9; qd++){
        int off = (qd/3 - 1)*PADY + (qd%3 - 1);
        uint32_t wq = (uint32_t)qd*32*XSTR;
        #pragma unroll
        for (int ks = 0; ks < 2; ks++){
            uint32_t Af[4], Bh[2][4], Bl[2][4];
            LDSM4(Af, a_base + off*XSTR + ks*32);
            #pragma unroll
            for (int ni = 0; ni < 2; ni++){
                uint32_t bd = sbase + CV_WH + wq + (b_row + ni*16)*XSTR + ks*32 + b_koff;
                LDSM4(Bh[ni], bd);
                LDSM4(Bl[ni], bd + (CV_WL - CV_WH));
            }
            #pragma unroll
            for (int nj = 0; nj < 4; nj++){
                uint32_t* BH = Bh[nj>>1] + 2*(nj&1);
                uint32_t* BL = Bl[nj>>1] + 2*(nj&1);
                MMA16816(acc[nj], Af, BH[0], BH[1]);
                MMA16816(acc[nj], Af, BL[0], BL[1]);
            }
        }
    }

    int g = lane >> 2, tig = lane & 3;
    int r0 = p0 + wid*16 + g;
    int r1 = r0 + 8;
    int y0 = r0 % PADY, y1 = r1 % PADY;
    bool v0 = (r0 < PPTOT) && (y0 >= 1) && (y0 <= 15);
    bool v1 = (r1 < PPTOT) && (y1 >= 1) && (y1 <= 15);

    #pragma unroll
    for (int nj = 0; nj < 4; nj++){
        int c0 = nj*8 + 2*tig, c1 = c0 + 1;
        float bc0 = (c0 < NC) ? cb[c0] : 0.f;
        float bc1 = (c1 < NC) ? cb[c1] : 0.f;
        float s0 = v0 ? fmaxf(acc[nj][0] + bc0, 0.f) : 0.f;
        float s1 = v0 ? fmaxf(acc[nj][1] + bc1, 0.f) : 0.f;
        float s2 = v1 ? fmaxf(acc[nj][2] + bc0, 0.f) : 0.f;
        float s3 = v1 ? fmaxf(acc[nj][3] + bc1, 0.f) : 0.f;
        float t0 = s0 + s2, t1 = s1 + s3;
        #pragma unroll
        for (int o = 16; o >= 4; o >>= 1){
            t0 += __shfl_down_sync(0xFFFFFFFFu, t0, o);
            t1 += __shfl_down_sync(0xFFFFFFFFu, t1, o);
        }
        if (lane < 4){
            if (c0 < NC) atomicAdd(&red[c0], t0);
            if (c1 < NC) atomicAdd(&red[c1], t1);
        }
    }
    __syncthreads();
    if (t < NC) atomicAdd(&g_ap[b*NC + t], red[t]);
}

__global__ void k_att(const float* __restrict__ fw, const float* __restrict__ fb){
    int b = blockIdx.x*blockDim.x + threadIdx.x;
    if (b < NB){
        float s = fb[0];
        #pragma unroll
        for (int c = 0; c < NC; c++) s = fmaf(g_ap[b*NC+c]*(1.0f/NP), fw[c], s);
        g_att[b] = 1.0f/(1.0f + expf(-s));
    }
}

// =====================================================================
// GEMM1: tall tile M=256 x N=64, W fp32 read once + in-kernel convert.
// A fp16 via 3-stage cp.async (wait_group 1); B fp32 reg-prefetch + cvt, 2-stage.
// =====================================================================
#define G2_ASTAGE 20480
#define G2_BOFF   (3*G2_ASTAGE)
#define G2_BSTAGE 5120
#define G2_SMEM   (3*G2_ASTAGE + 2*G2_BSTAGE)

__global__ void __launch_bounds__(256, 2) k_gemm1_mma(const float* __restrict__ W){
    extern __shared__ char smem[];
    uint32_t sbase = smem_u32(smem);
    int t = threadIdx.x;
    int wid = t >> 5, lane = t & 31;
    int n0 = blockIdx.x*64, z = blockIdx.y;
    int c0 = (z*NCH32)/SPLITK1, c1 = ((z+1)*NCH32)/SPLITK1;

    int m_w = (wid & 3)*64;
    int n_w = (wid >> 2)*32;

    const __half* Asrc = g_Ah + (size_t)t*KPADH;
    uint32_t a_dst = (uint32_t)t*80;
    int rb = t >> 2, seg = t & 3;
    int brow = n0 + rb;
    const float* Bsrc = W + (size_t)((brow < NH1) ? brow : (NH1-1))*KTOT + seg*8;
    uint32_t b_dst = G2_BOFF + (uint32_t)rb*80 + (uint32_t)seg*16;

    float acc[4][4][4];
    #pragma unroll
    for (int mi = 0; mi < 4; mi++)
        #pragma unroll
        for (int nj = 0; nj < 4; nj++)
            #pragma unroll
            for (int q = 0; q < 4; q++) acc[mi][nj][q] = 0.f;

    {
        uint32_t d = sbase + a_dst;
        const char* sp = (const char*)(Asrc + c0*32);
        CP16(d, sp); CP16(d+16, sp+16); CP16(d+32, sp+32); CP16(d+48, sp+48);
        CP_COMMIT();
        if (c0 + 1 < c1){
            uint32_t d1 = sbase + G2_ASTAGE + a_dst;
            const char* sp1 = (const char*)(Asrc + (c0+1)*32);
            CP16(d1, sp1); CP16(d1+16, sp1+16); CP16(d1+32, sp1+32); CP16(d1+48, sp1+48);
            CP_COMMIT();
        }
        float2 vb[4];
        int kbase = c0*32 + seg*8;
        #pragma unroll
        for (int j = 0; j < 4; j++){
            int kg = kbase + 2*j;
            vb[j] = (kg < KTOT) ? *(const float2*)(Bsrc + c0*32 + 2*j) : make_float2(0.f, 0.f);
        }
        __half2 p0 = __floats2half2_rn(vb[0].x, vb[0].y);
        __half2 p1 = __floats2half2_rn(vb[1].x, vb[1].y);
        __half2 p2 = __floats2half2_rn(vb[2].x, vb[2].y);
        __half2 p3 = __floats2half2_rn(vb[3].x, vb[3].y);
        uint4 u = make_uint4(*(uint32_t*)&p0, *(uint32_t*)&p1, *(uint32_t*)&p2, *(uint32_t*)&p3);
        *(uint4*)(smem + b_dst) = u;
    }

    uint32_t a_row = (uint32_t)(m_w + (lane & 15));
    uint32_t a_koff = ((lane >> 4) & 1)*16;
    uint32_t b_row = (uint32_t)(n_w + ((lane >> 4) & 1)*8 + (lane & 7));
    uint32_t b_koff = ((lane >> 3) & 1)*16;

    for (int c = c0; c < c1; c++){
        int rel = c - c0;
        uint32_t sa = sbase + (uint32_t)(rel % 3)*G2_ASTAGE;
        uint32_t sbB = sbase + (uint32_t)(rel & 1)*G2_BSTAGE;
        bool more = (c + 1 < c1);

        CP_WAIT1();
        __syncthreads();

        if (c + 2 < c1){
            uint32_t d = sbase + (uint32_t)((rel + 2) % 3)*G2_ASTAGE + a_dst;
            const char* sp = (const char*)(Asrc + (c+2)*32);
            CP16(d, sp); CP16(d+16, sp+16); CP16(d+32, sp+32); CP16(d+48, sp+48);
            CP_COMMIT();
        }
        float2 vb[4];
        if (more){
            #pragma unroll
            for (int j = 0; j < 4; j++){
                int kg = (c+1)*32 + seg*8 + 2*j;
                vb[j] = (kg < KTOT) ? *(const float2*)(Bsrc + (c+1)*32 + 2*j) : make_float2(0.f, 0.f);
            }
        }

        #pragma unroll
        for (int ks = 0; ks < 2; ks++){
            uint32_t ksb = ks*32;
            uint32_t Ah[4][4], Bh[2][4];
            #pragma unroll
            for (int mi = 0; mi < 4; mi++){
                uint32_t ad = sa + (a_row + mi*16)*80 + ksb + a_koff;
                LDSM4(Ah[mi], ad);
            }
            #pragma unroll
            for (int ni = 0; ni < 2; ni++){
                uint32_t bd = sbB + G2_BOFF + (b_row + ni*16)*80 + ksb + b_koff;
                LDSM4(Bh[ni], bd);
            }
            #pragma unroll
            for (int mi = 0; mi < 4; mi++)
                #pragma unroll
                for (int nj = 0; nj < 4; nj++){
                    uint32_t* BH = Bh[nj>>1] + 2*(nj&1);
                    MMAF16(acc[mi][nj], Ah[mi], BH[0], BH[1]);
                }
        }

        if (more){
            __half2 p0 = __floats2half2_rn(vb[0].x, vb[0].y);
            __half2 p1 = __floats2half2_rn(vb[1].x, vb[1].y);
            __half2 p2 = __floats2half2_rn(vb[2].x, vb[2].y);
            __half2 p3 = __floats2half2_rn(vb[3].x, vb[3].y);
            uint4 u = make_uint4(*(uint32_t*)&p0, *(uint32_t*)&p1, *(uint32_t*)&p2, *(uint32_t*)&p3);
            *(uint4*)(smem + ((rel+1) & 1)*G2_BSTAGE + b_dst) = u;
        }
    }

    int g = lane >> 2, tig = lane & 3;
    #pragma unroll
    for (int mi = 0; mi < 4; mi++){
        int mrow = m_w + mi*16 + g;
        #pragma unroll
        for (int nj = 0; nj < 4; nj++){
            int ncol = n0 + n_w + nj*8 + 2*tig;
            if (ncol < NH1){
                float* d0 = g_Cp + ((size_t)z*NB + mrow)*NH1 + ncol;
                *(float2*)d0 = make_float2(acc[mi][nj][0], acc[mi][nj][1]);
                float* d1 = d0 + (size_t)8*NH1;
                *(float2*)d1 = make_float2(acc[mi][nj][2], acc[mi][nj][3]);
            }
        }
    }
}

__global__ void k_comb1(const float* __restrict__ b1){
    int i = blockIdx.x*256 + threadIdx.x;
    if (i >= NB*NH1) return;
    int b = i/NH1, j = i - b*NH1;
    float v = 0.f;
    #pragma unroll
    for (int z = 0; z < SPLITK1; z++) v += g_Cp[(size_t)z*NB*NH1 + i];
    v = v * g_att[b] + b1[j];
    g_C[i] = (v > 0.f) ? v : 0.01f*v;
}

// ---------------- small split-K tiled SGEMM for layer 2 ----------------
template<int SPLITK>
__global__ void __launch_bounds__(256) k_gemm(const float* __restrict__ Bmat, int N, int K){
    const float* A = g_C;
    int n0 = blockIdx.x*64, m0 = blockIdx.y*64, z = blockIdx.z;
    int ck = (K + SPLITK - 1)/SPLITK;
    int k0 = z*ck, kend = min(K, k0 + ck);
    __shared__ float As[64][17], Bs[64][17];
    float acc[4][4];
    #pragma unroll
    for (int mi = 0; mi < 4; mi++)
        #pragma unroll
        for (int ni = 0; ni < 4; ni++) acc[mi][ni] = 0.f;
    int tr = threadIdx.x >> 4, tc = threadIdx.x & 15;
    for (int kt = k0; kt < kend; kt += 16){
        #pragma unroll
        for (int l = 0; l < 4; l++){
            int i = threadIdx.x + l*256;
            int rr = i >> 4, cc = i & 15;
            int k = kt + cc;
            As[rr][cc] = (k < kend) ? A[(size_t)(m0+rr)*K + k] : 0.f;
            int j = n0 + rr;
            Bs[rr][cc] = (k < kend && j < N) ? Bmat[(size_t)j*K + k] : 0.f;
        }
        __syncthreads();
        #pragma unroll
        for (int kk = 0; kk < 16; kk++){
            float a[4], bb[4];
            #pragma unroll
            for (int mi = 0; mi < 4; mi++) a[mi]  = As[tr*4+mi][kk];
            #pragma unroll
            for (int ni = 0; ni < 4; ni++) bb[ni] = Bs[tc*4+ni][kk];
            #pragma unroll
            for (int mi = 0; mi < 4; mi++)
                #pragma unroll
                for (int ni = 0; ni < 4; ni++) acc[mi][ni] = fmaf(a[mi], bb[ni], acc[mi][ni]);
        }
        __syncthreads();
    }
    #pragma unroll
    for (int mi = 0; mi < 4; mi++)
        #pragma unroll
        for (int ni = 0; ni < 4; ni++){
            int m = m0 + tr*4 + mi, n = n0 + tc*4 + ni;
            if (n < N) g_Cp[(size_t)z*NB*N + (size_t)m*N + n] = acc[mi][ni];
        }
}

__global__ void k_comb2(const float* __restrict__ b2){
    int i = blockIdx.x*256 + threadIdx.x;
    if (i >= NB*NO) return;
    int j = i % NO;
    float v = b2[j];
    #pragma unroll
    for (int z = 0; z < 8; z++) v += g_Cp[(size_t)z*NB*NO + i];
    g_x1[i] = v;
}

__global__ void k_head(const float* __restrict__ x, const float* __restrict__ rw,
                       const float* __restrict__ rb, float* __restrict__ out){
    int b = blockIdx.x, t = threadIdx.x;
    float x0 = (x[(size_t)b*SXv*(SYv+1) + t*(SYv+1) + SYv] - 400.0f)*0.01f;
    float v = g_x1[b*NO + t]*rw[2*t] + x0*rw[2*t+1];
    __shared__ float s[128];
    s[t] = v; __syncthreads();
    for (int o = 64; o > 0; o >>= 1){ if (t < o) s[t] += s[t+o]; __syncthreads(); }
    if (t == 0) out[b] = s[0] + rb[0];
}

// ---------------- launch ----------------
extern "C" void kernel_launch(void* const* d_in, const int* in_sizes, int n_in,
                              void* d_out, int out_size){
    const float* x      = (const float*)d_in[0];
    const float* p_w    = (const float*)d_in[1];
    const float* p_b    = (const float*)d_in[2];
    const float* sc0_w1 = (const float*)d_in[3];
    const float* sc0_w2 = (const float*)d_in[4];
    const float* sc1_w1 = (const float*)d_in[5];
    const float* sc1_w2 = (const float*)d_in[6];
    const float* mlp0_w1= (const float*)d_in[7];
    const float* mlp0_b1= (const float*)d_in[8];
    const float* mlp0_w2= (const float*)d_in[9];
    const float* mlp0_b2= (const float*)d_in[10];
    const float* mlp1_w1= (const float*)d_in[11];
    const float* mlp1_b1= (const float*)d_in[12];
    const float* mlp1_w2= (const float*)d_in[13];
    const float* mlp1_b2= (const float*)d_in[14];
    const float* w0_w   = (const float*)d_in[15];
    const float* w0_b   = (const float*)d_in[16];
    const float* w1_w   = (const float*)d_in[17];
    const float* w1_b   = (const float*)d_in[18];
    const float* sa_cw  = (const float*)d_in[19];
    const float* sa_cb  = (const float*)d_in[20];
    const float* sa_fw  = (const float*)d_in[21];
    const float* sa_fb  = (const float*)d_in[22];
    const float* o1_w1  = (const float*)d_in[23];
    const float* o1_b1  = (const float*)d_in[24];
    const float* o1_w2  = (const float*)d_in[25];
    const float* o1_b2  = (const float*)d_in[26];
    const float* reg2_w = (const float*)d_in[27];
    const float* reg2_b = (const float*)d_in[28];
    float* out = (float*)d_out;

    cudaFuncSetAttribute(k_gemm1_mma, cudaFuncAttributeMaxDynamicSharedMemorySize, G2_SMEM);
    cudaFuncSetAttribute(k_conv_tc,   cudaFuncAttributeMaxDynamicSharedMemorySize, CV_SMEM);

    k_twiddle<<<28, 256>>>();

    // Fourier block 0
    k_fdft<<<NB*NC, 256>>>(x, p_w, p_b, 1);
    k_mix<<<dim3(NB, 4), 256>>>(sc0_w1, sc0_w2);
    k_idft<<<NB*NC, 256>>>();
    k_fuse<<<dim3((NP+255)/256, NB), 256>>>(mlp0_w1, mlp0_b1, mlp0_w2, mlp0_b2, w0_w, w0_b, 0);

    // Fourier block 1 (fuse writes ONLY fp16 A)
    k_fdft<<<NB*NC, 256>>>(x, p_w, p_b, 0);
    k_mix<<<dim3(NB, 4), 256>>>(sc1_w1, sc1_w2);
    k_idft<<<NB*NC, 256>>>();
    k_fuse<<<dim3((NP+255)/256, NB), 256>>>(mlp1_w1, mlp1_b1, mlp1_w2, mlp1_b2, w1_w, w1_b, 1);

    // ---- fork: spatial attention on side stream (reads g_Ah) ----
    cudaEventRecord(g_sp.eFuse, 0);
    cudaStreamWaitEvent(g_sp.s2, g_sp.eFuse, 0);
    k_conv_tc<<<dim3(NTILE, NB), 256, CV_SMEM, g_sp.s2>>>(sa_cw, sa_cb);
    k_att<<<1, 256, 0, g_sp.s2>>>(sa_fw, sa_fb);
    cudaEventRecord(g_sp.eAtt, g_sp.s2);

    // main stream: big GEMM
    k_gemm1_mma<<<dim3(44, SPLITK1), 256, G2_SMEM>>>(o1_w1);

    cudaStreamWaitEvent(0, g_sp.eAtt, 0);
    k_comb1<<<(NB*NH1+255)/256, 256>>>(o1_b1);
    k_gemm<8><<<dim3(2, 4, 8), 256>>>(o1_w2, NO, 2808);
    k_comb2<<<(NB*NO+255)/256, 256>>>(o1_b2);
    k_head<<<NB, 128>>>(x, reg2_w, reg2_b, out);
}

// round 17
// speedup vs baseline: 1.1025x; 1.0851x over previous
#include <cuda_runtime.h>
#include <cuda_fp16.h>
#include <math.h>
#include <stdint.h>

#define NB 256
#define NC 26
#define SXv 179
#define SYv 15
#define NP (SXv*SYv)          // 2685
#define MM 7
#define NMODE (14*MM)         // 98
#define KTOT (NC*NP)          // 69810
#define KPADH 69824           // padded to /64 (16B-aligned fp16 rows)
#define NH1 2808
#define NO 128
#define NCH32 2182            // ceil(69810/32)
#define SPLITK1 13

// ---------------- device scratch ----------------
__device__ float  g_h [NB*NC*NP];
__device__ float  g_t2[NB*NC*NP];
__device__ float2 g_F [NB*NC*NMODE];
__device__ float2 g_G [NB*NC*NMODE];
__device__ float2 g_txf[14*SXv];
__device__ float2 g_txi[14*SXv];
__device__ float2 g_twyf[MM*SYv];
__device__ float2 g_twy2[MM*SYv];
__device__ float  g_ap [NB*NC];
__device__ float  g_att[NB];
__device__ float  g_Cp [SPLITK1*NB*NH1];
__device__ float  g_C  [NB*NH1];
__device__ float  g_x1 [NB*NO];
__device__ __half g_Ah[(size_t)NB*KPADH];    // 35.8 MB

// ---------------- host-side stream/event pack ----------------
struct SidePack {
    cudaStream_t s2;
    cudaEvent_t eFuse, eAtt;
    SidePack(){
        cudaStreamCreateWithFlags(&s2, cudaStreamNonBlocking);
        cudaEventCreateWithFlags(&eFuse, cudaEventDisableTiming);
        cudaEventCreateWithFlags(&eAtt,  cudaEventDisableTiming);
    }
};
static SidePack g_sp;

__device__ __forceinline__ float gelu_f(float x){
    return 0.5f*x*(1.0f + erff(x*0.70710678118654752f));
}

__device__ __forceinline__ uint32_t smem_u32(const void* p){
    uint32_t a;
    asm("{ .reg .u64 t; cvta.to.shared.u64 t, %1; cvt.u32.u64 %0, t; }" : "=r"(a) : "l"(p));
    return a;
}

__device__ __forceinline__ void block_reduce2(float s, float q, float* shm,
                                              float& osum, float& osq){
    int t = threadIdx.x, lane = t & 31, wid = t >> 5;
    #pragma unroll
    for (int o = 16; o > 0; o >>= 1){
        s += __shfl_down_sync(0xFFFFFFFFu, s, o);
        q += __shfl_down_sync(0xFFFFFFFFu, q, o);
    }
    if (lane == 0){ shm[wid] = s; shm[8 + wid] = q; }
    __syncthreads();
    if (t == 0){
        float ss = 0.f, qq = 0.f;
        #pragma unroll
        for (int i = 0; i < 8; i++){ ss += shm[i]; qq += shm[8 + i]; }
        shm[16] = ss; shm[17] = qq;
    }
    __syncthreads();
    osum = shm[16]; osq = shm[17];
}

// ---------------- twiddle tables + g_ap zero + g_Ah padding ----------------
__global__ void k_twiddle(){
    int i = blockIdx.x*blockDim.x + threadIdx.x;
    if (i < 14*SXv){
        int k1i = i/SXv, xx = i%SXv;
        int keff = (k1i < 7) ? k1i : (14 - k1i);
        float sn, cs;
        sincospif(2.0f*(float)(keff*xx)/179.0f, &sn, &cs);
        g_txf[i] = make_float2(cs, (k1i < 7) ? -sn : sn);
        g_txi[i] = make_float2(cs, (k1i < 7) ? sn : -sn);
    }
    if (i < MM*SYv){
        int k = i/SYv, y = i%SYv;
        float sn, cs;
        sincospif(2.0f*(float)(k*y)/15.0f, &sn, &cs);
        g_twyf[i] = make_float2(cs, -sn);
        g_twy2[i] = make_float2(2.f*cs, 2.f*sn);
    }
    if (i < NB*NC) g_ap[i] = 0.f;
    if (i < NB*(KPADH - KTOT)){
        int row = i/(KPADH - KTOT), col = KTOT + i%(KPADH - KTOT);
        g_Ah[(size_t)row*KPADH + col] = __float2half(0.f);
    }
}

// ---------------- fused lift + instance-norm + forward truncated DFT ----------------
__global__ void __launch_bounds__(256) k_fdft(const float* __restrict__ x,
                                              const float* __restrict__ pw,
                                              const float* __restrict__ pb,
                                              int first){
    int bc = blockIdx.x;
    __shared__ float  sp[NP];
    __shared__ float2 Ys[SXv*MM];
    __shared__ float2 Pp[2*NMODE];
    __shared__ float  red[18];
    int t = threadIdx.x;

    float s = 0.f, q = 0.f;
    if (first){
        int b = bc / NC, w = bc % NC;
        float w0 = pw[w*3+0], w1 = pw[w*3+1], w2 = pw[w*3+2], bb = pb[w];
        const float* xb = x + (size_t)b*SXv*(SYv+1);
        float* outp = g_h + (size_t)bc*NP;
        for (int p = t; p < NP; p += 256){
            int xi = p/SYv, yi = p%SYv;
            float u = xb[xi*(SYv+1) + yi];
            float v = u*w0 + ((float)xi*(1.0f/178.0f))*w1 + ((float)yi*(1.0f/14.0f))*w2 + bb;
            outp[p] = v;
            sp[p] = v;
            s += v; q += v*v;
        }
    } else {
        const float* src = g_h + (size_t)bc*NP;
        for (int p = t; p < NP; p += 256){
            float v = src[p];
            sp[p] = v;
            s += v; q += v*v;
        }
    }
    __syncthreads();
    float sum, sq;
    block_reduce2(s, q, red, sum, sq);
    float mu  = sum * (1.0f/NP);
    float var = sq * (1.0f/NP) - mu*mu;
    float inv = rsqrtf(var + 1e-5f);
    for (int p = t; p < NP; p += 256) sp[p] = (sp[p] - mu)*inv;
    __syncthreads();

    // y-DFT: thread owns k2 = t%7, iterates xx; twiddles register-hoisted
    if (t < 252){
        int k2 = t % 7;
        float twr[SYv], twi[SYv];
        #pragma unroll
        for (int y = 0; y < SYv; y++){
            float2 tw = g_twyf[k2*SYv + y];
            twr[y] = tw.x; twi[y] = tw.y;
        }
        for (int xx = t/7; xx < SXv; xx += 36){
            float re = 0.f, im = 0.f;
            #pragma unroll
            for (int y = 0; y < SYv; y++){
                float v = sp[xx*SYv + y];
                re = fmaf(v, twr[y], re);
                im = fmaf(v, twi[y], im);
            }
            Ys[xx*MM + k2] = make_float2(re, im);
        }
    }
    __syncthreads();

    if (t < 2*NMODE){
        int mode = t >> 1, half = t & 1;
        int k1i = mode/MM, k2 = mode%MM;
        const float2* tw = g_txf + k1i*SXv;
        int xa = half ? 90 : 0, xbnd = half ? SXv : 90;
        float re = 0.f, im = 0.f;
        #pragma unroll 3
        for (int xx = xa; xx < xbnd; xx++){
            float2 u = tw[xx];
            float2 y = Ys[xx*MM + k2];
            re += y.x*u.x - y.y*u.y;
            im += y.x*u.y + y.y*u.x;
        }
        Pp[t] = make_float2(re, im);
    }
    __syncthreads();
    if (t < NMODE){
        float2 a = Pp[2*t], b2 = Pp[2*t+1];
        g_F[(size_t)bc*NMODE + t] = make_float2(a.x + b2.x, a.y + b2.y);
    }
}

// ---------------- complex channel mix (g_F -> g_G) ----------------
__global__ void k_mix(const float* __restrict__ w1, const float* __restrict__ w2){
    int b = blockIdx.x, seg = blockIdx.y;
    __shared__ float2 Fs[NC*NMODE];
    for (int i = threadIdx.x; i < NC*NMODE; i += 256)
        Fs[i] = g_F[(size_t)b*NC*NMODE + i];
    __syncthreads();
    int s0 = (seg*NC*NMODE) >> 2, s1 = ((seg+1)*NC*NMODE) >> 2;
    for (int oi = s0 + threadIdx.x; oi < s1; oi += 256){
        int o = oi/NMODE, mode = oi%NMODE;
        int k1i = mode/MM, k2 = mode%MM;
        const float2* wp;
        if (k1i < 7) wp = (const float2*)w1 + ((size_t)(o*MM + k1i)*MM + k2);
        else         wp = (const float2*)w2 + ((size_t)(o*MM + (k1i-7))*MM + k2);
        float re = 0.f, im = 0.f;
        #pragma unroll 2
        for (int i = 0; i < NC; i++){
            float2 f = Fs[i*NMODE + mode];
            float2 w = *wp;
            re += f.x*w.x - f.y*w.y;
            im += f.x*w.y + f.y*w.x;
            wp += NC*MM*MM;
        }
        g_G[(size_t)b*NC*NMODE + oi] = make_float2(re, im);
    }
}

// ---------------- fused inverse truncated DFT + instance norm ----------------
// L1-traffic-restructured: register-hoisted invariant operands per phase.
__global__ void __launch_bounds__(256) k_idft(){
    int bc = blockIdx.x;
    __shared__ float2 Gs[NMODE];
    __shared__ float2 Ss[SXv*MM];
    __shared__ float  pl[NP];
    __shared__ float  red[18];
    int t = threadIdx.x;
    if (t < NMODE){
        float2 g = g_G[(size_t)bc*NMODE + t];
        Gs[t] = make_float2(g.x*(1.0f/(179.0f*15.0f)), g.y*(1.0f/(179.0f*15.0f)));
    }
    __syncthreads();

    // x-expansion: thread owns k2, iterates n1; Gs register-hoisted
    if (t < 252){
        int k2 = t % 7;
        float gr[14], gi[14];
        #pragma unroll
        for (int k1i = 0; k1i < 14; k1i++){
            float2 g = Gs[k1i*MM + k2];
            gr[k1i] = g.x; gi[k1i] = g.y;
        }
        for (int n1 = t/7; n1 < SXv; n1 += 36){
            float re = 0.f, im = 0.f;
            #pragma unroll
            for (int k1i = 0; k1i < 14; k1i++){
                float2 u = g_txi[k1i*SXv + n1];
                re += gr[k1i]*u.x - gi[k1i]*u.y;
                im += gr[k1i]*u.y + gi[k1i]*u.x;
            }
            Ss[n1*MM + k2] = make_float2(re, im);
        }
    }
    __syncthreads();

    // y C2R + stats: thread owns n2, iterates n1; twy2 register-hoisted
    float s = 0.f, q = 0.f;
    if (t < 240){
        int n2 = t % SYv;
        float twr[6], twi[6];
        #pragma unroll
        for (int k2 = 1; k2 < MM; k2++){
            float2 w = g_twy2[k2*SYv + n2];
            twr[k2-1] = w.x; twi[k2-1] = w.y;
        }
        for (int n1 = t/SYv; n1 < SXv; n1 += 16){
            float val = Ss[n1*MM].x;
            #pragma unroll
            for (int k2 = 1; k2 < MM; k2++){
                float2 sv = Ss[n1*MM + k2];
                val += sv.x*twr[k2-1] - sv.y*twi[k2-1];
            }
            pl[n1*SYv + n2] = val;
            s += val; q += val*val;
        }
    }
    __syncthreads();
    float sum, sq;
    block_reduce2(s, q, red, sum, sq);
    float mu  = sum * (1.0f/NP);
    float var = sq * (1.0f/NP) - mu*mu;
    float inv = rsqrtf(var + 1e-5f);
    float* d = g_t2 + (size_t)bc*NP;
    for (int p = t; p < NP; p += 256) d[p] = (pl[p] - mu)*inv;
}

// ---------------- fused: h = gelu( mlp(g_t2) + c1(h) ), optional fp16 A output ----------------
__global__ void __launch_bounds__(256) k_fuse(
        const float* __restrict__ w1, const float* __restrict__ b1,
        const float* __restrict__ w2, const float* __restrict__ b2,
        const float* __restrict__ wr, const float* __restrict__ br,
        int writeAh){
    __shared__ float sw1[NC*NC], sw2[NC*NC], swr[NC*NC], sb1[NC], sb2[NC], sbr[NC];
    int t = threadIdx.x;
    for (int i = t; i < NC*NC; i += 256){ sw1[i] = w1[i]; sw2[i] = w2[i]; swr[i] = wr[i]; }
    if (t < NC){ sb1[t] = b1[t]; sb2[t] = b2[t]; sbr[t] = br[t]; }
    __syncthreads();
    int p = blockIdx.x*256 + t;
    if (p >= NP) return;
    int b = blockIdx.y;
    size_t base = (size_t)b*NC*NP + p;
    float xin[NC], tm[NC];
    #pragma unroll
    for (int i = 0; i < NC; i++) xin[i] = g_t2[base + (size_t)i*NP];
    #pragma unroll
    for (int o = 0; o < NC; o++){
        float a = sb1[o];
        #pragma unroll
        for (int i = 0; i < NC; i++) a = fmaf(xin[i], sw1[o*NC+i], a);
        tm[o] = gelu_f(a);
    }
    float hin[NC];
    #pragma unroll
    for (int i = 0; i < NC; i++) hin[i] = g_h[base + (size_t)i*NP];
    __half* ahp = g_Ah + (size_t)b*KPADH + p;
    #pragma unroll
    for (int o = 0; o < NC; o++){
        float a = sb2[o] + sbr[o];
        #pragma unroll
        for (int i = 0; i < NC; i++) a = fmaf(tm[i],  sw2[o*NC+i], a);
        #pragma unroll
        for (int i = 0; i < NC; i++) a = fmaf(hin[i], swr[o*NC+i], a);
        float gv = gelu_f(a);
        g_h[base + (size_t)o*NP] = gv;
        if (writeAh) ahp[(size_t)o*NP] = __float2half(gv);
    }
}

// =====================================================================
// Tensor-core conv3x3 + relu + pooling (fused) — reads g_h fp32 (R14 behavior)
// =====================================================================
#define PADY 17
#define PPTOT (SXv*PADY)
#define CTM 128
#define NTILE 24
#define CROWS (CTM + 36)
#define XSTR 80
#define CV_XS 0
#define CV_WH (CROWS*XSTR)
#define CV_WL (CV_WH + 9*32*XSTR)
#define CV_RED (CV_WL + 9*32*XSTR)
#define CV_SMEM (CV_RED + 128)

#define LDSM4(R, ADDR) \
    asm volatile("ldmatrix.sync.aligned.m8n8.x4.shared.b16 {%0,%1,%2,%3}, [%4];" \
        : "=r"((R)[0]), "=r"((R)[1]), "=r"((R)[2]), "=r"((R)[3]) : "r"(ADDR))

#define MMA16816(D, A, B0, B1) \
    asm volatile("mma.sync.aligned.m16n8k16.row.col.f32.bf16.bf16.f32 " \
        "{%0,%1,%2,%3}, {%4,%5,%6,%7}, {%8,%9}, {%0,%1,%2,%3};" \
        : "+f"((D)[0]), "+f"((D)[1]), "+f"((D)[2]), "+f"((D)[3]) \
        : "r"((A)[0]), "r"((A)[1]), "r"((A)[2]), "r"((A)[3]), "r"(B0), "r"(B1))

#define MMAF16(D, A, B0, B1) \
    asm volatile("mma.sync.aligned.m16n8k16.row.col.f32.f16.f16.f32 " \
        "{%0,%1,%2,%3}, {%4,%5,%6,%7}, {%8,%9}, {%0,%1,%2,%3};" \
        : "+f"((D)[0]), "+f"((D)[1]), "+f"((D)[2]), "+f"((D)[3]) \
        : "r"((A)[0]), "r"((A)[1]), "r"((A)[2]), "r"((A)[3]), "r"(B0), "r"(B1))

#define CP16(dst, src) asm volatile("cp.async.cg.shared.global [%0], [%1], 16;" :: "r"(dst), "l"(src) : "memory")
#define CP_COMMIT() asm volatile("cp.async.commit_group;" ::: "memory")
#define CP_WAIT0()  asm volatile("cp.async.wait_group 0;" ::: "memory")
#define CP_WAIT1()  asm volatile("cp.async.wait_group 1;" ::: "memory")

__global__ void __launch_bounds__(256) k_conv_tc(const float* __restrict__ cw,
                                                 const float* __restrict__ cb){
    extern __shared__ char smem[];
    uint32_t sbase = smem_u32(smem);
    float* red = (float*)(smem + CV_RED);
    int t = threadIdx.x;
    int wid = t >> 5, lane = t & 31;
    int tile = blockIdx.x, b = blockIdx.y;
    int p0 = tile*CTM;

    if (t < 32) red[t] = 0.f;

    for (int idx = t; idx < 9*32*32; idx += 256){
        int qd = idx >> 10, rem = idx & 1023;
        int o = rem >> 5, i = rem & 31;
        float v = (o < NC && i < NC) ? cw[(o*NC + i)*9 + qd] : 0.f;
        uint32_t hr;
        asm("cvt.rn.bf16x2.f32 %0, %1, %2;" : "=r"(hr) : "f"(0.f), "f"(v));
        float hi_f = __uint_as_float(hr << 16);
        float lo_f = v - hi_f;
        uint32_t lr;
        asm("cvt.rn.bf16x2.f32 %0, %1, %2;" : "=r"(lr) : "f"(0.f), "f"(lo_f));
        uint32_t off = (uint32_t)qd*32*XSTR + (uint32_t)o*XSTR + (uint32_t)i*2;
        *(uint16_t*)(smem + CV_WH + off) = (uint16_t)(hr & 0xFFFF);
        *(uint16_t*)(smem + CV_WL + off) = (uint16_t)(lr & 0xFFFF);
    }

    const float* hb_ptr = g_h + (size_t)b*NC*NP;
    for (int idx = t; idx < CROWS*32; idx += 256){
        int c = idx / CROWS, row = idx % CROWS;
        int pp = p0 - 18 + row;
        float v = 0.f;
        if (c < NC && pp >= 0 && pp < PPTOT){
            int xx = pp / PADY, yy = pp % PADY;
            if (yy >= 1 && yy <= 15) v = hb_ptr[(size_t)c*NP + xx*SYv + (yy-1)];
        }
        uint32_t r2;
        asm("cvt.rn.bf16x2.f32 %0, %1, %2;" : "=r"(r2) : "f"(0.f), "f"(v));
        *(uint16_t*)(smem + CV_XS + (uint32_t)row*XSTR + (uint32_t)c*2) = (uint16_t)(r2 & 0xFFFF);
    }
    __syncthreads();

    float acc[4][4];
    #pragma unroll
    for (int nj = 0; nj < 4; nj++)
        #pragma unroll
        for (int qd = 0; qd < 4; qd++) acc[nj][qd] = 0.f;

    uint32_t a_base = sbase + CV_XS + (uint32_t)(18 + wid*16 + (lane & 15))*XSTR + ((lane >> 4)*16);
    uint32_t b_row = (uint32_t)(((lane >> 4) & 1)*8 + (lane & 7));
    uint32_t b_koff = ((lane >> 3) & 1)*16;

    #pragma unroll
    for (int qd = 0; qd < 9; qd++){
        int off = (qd/3 - 1)*PADY + (qd%3 - 1);
        uint32_t wq = (uint32_t)qd*32*XSTR;
        #pragma unroll
        for (int ks = 0; ks < 2; ks++){
            uint32_t Af[4], Bh[2][4], Bl[2][4];
            LDSM4(Af, a_base + off*XSTR + ks*32);
            #pragma unroll
            for (int ni = 0; ni < 2; ni++){
                uint32_t bd = sbase + CV_WH + wq + (b_row + ni*16)*XSTR + ks*32 + b_koff;
                LDSM4(Bh[ni], bd);
                LDSM4(Bl[ni], bd + (CV_WL - CV_WH));
            }
            #pragma unroll
            for (int nj = 0; nj < 4; nj++){
                uint32_t* BH = Bh[nj>>1] + 2*(nj&1);
                uint32_t* BL = Bl[nj>>1] + 2*(nj&1);
                MMA16816(acc[nj], Af, BH[0], BH[1]);
                MMA16816(acc[nj], Af, BL[0], BL[1]);
            }
        }
    }

    int g = lane >> 2, tig = lane & 3;
    int r0 = p0 + wid*16 + g;
    int r1 = r0 + 8;
    int y0 = r0 % PADY, y1 = r1 % PADY;
    bool v0 = (r0 < PPTOT) && (y0 >= 1) && (y0 <= 15);
    bool v1 = (r1 < PPTOT) && (y1 >= 1) && (y1 <= 15);

    #pragma unroll
    for (int nj = 0; nj < 4; nj++){
        int c0 = nj*8 + 2*tig, c1 = c0 + 1;
        float bc0 = (c0 < NC) ? cb[c0] : 0.f;
        float bc1 = (c1 < NC) ? cb[c1] : 0.f;
        float s0 = v0 ? fmaxf(acc[nj][0] + bc0, 0.f) : 0.f;
        float s1 = v0 ? fmaxf(acc[nj][1] + bc1, 0.f) : 0.f;
        float s2 = v1 ? fmaxf(acc[nj][2] + bc0, 0.f) : 0.f;
        float s3 = v1 ? fmaxf(acc[nj][3] + bc1, 0.f) : 0.f;
        float t0 = s0 + s2, t1 = s1 + s3;
        #pragma unroll
        for (int o = 16; o >= 4; o >>= 1){
            t0 += __shfl_down_sync(0xFFFFFFFFu, t0, o);
            t1 += __shfl_down_sync(0xFFFFFFFFu, t1, o);
        }
        if (lane < 4){
            if (c0 < NC) atomicAdd(&red[c0], t0);
            if (c1 < NC) atomicAdd(&red[c1], t1);
        }
    }
    __syncthreads();
    if (t < NC) atomicAdd(&g_ap[b*NC + t], red[t]);
}

__global__ void k_att(const float* __restrict__ fw, const float* __restrict__ fb){
    int b = blockIdx.x*blockDim.x + threadIdx.x;
    if (b < NB){
        float s = fb[0];
        #pragma unroll
        for (int c = 0; c < NC; c++) s = fmaf(g_ap[b*NC+c]*(1.0f/NP), fw[c], s);
        g_att[b] = 1.0f/(1.0f + expf(-s));
    }
}

// =====================================================================
// GEMM1: tall tile M=256 x N=64, W fp32 read once + in-kernel convert.
// A fp16 via 3-stage cp.async (wait_group 1); B fp32 reg-prefetch + cvt, 2-stage.
// =====================================================================
#define G2_ASTAGE 20480
#define G2_BOFF   (3*G2_ASTAGE)
#define G2_BSTAGE 5120
#define G2_SMEM   (3*G2_ASTAGE + 2*G2_BSTAGE)

__global__ void __launch_bounds__(256, 2) k_gemm1_mma(const float* __restrict__ W){
    extern __shared__ char smem[];
    uint32_t sbase = smem_u32(smem);
    int t = threadIdx.x;
    int wid = t >> 5, lane = t & 31;
    int n0 = blockIdx.x*64, z = blockIdx.y;
    int c0 = (z*NCH32)/SPLITK1, c1 = ((z+1)*NCH32)/SPLITK1;

    int m_w = (wid & 3)*64;
    int n_w = (wid >> 2)*32;

    const __half* Asrc = g_Ah + (size_t)t*KPADH;
    uint32_t a_dst = (uint32_t)t*80;
    int rb = t >> 2, seg = t & 3;
    int brow = n0 + rb;
    const float* Bsrc = W + (size_t)((brow < NH1) ? brow : (NH1-1))*KTOT + seg*8;
    uint32_t b_dst = G2_BOFF + (uint32_t)rb*80 + (uint32_t)seg*16;

    float acc[4][4][4];
    #pragma unroll
    for (int mi = 0; mi < 4; mi++)
        #pragma unroll
        for (int nj = 0; nj < 4; nj++)
            #pragma unroll
            for (int q = 0; q < 4; q++) acc[mi][nj][q] = 0.f;

    {
        uint32_t d = sbase + a_dst;
        const char* sp = (const char*)(Asrc + c0*32);
        CP16(d, sp); CP16(d+16, sp+16); CP16(d+32, sp+32); CP16(d+48, sp+48);
        CP_COMMIT();
        if (c0 + 1 < c1){
            uint32_t d1 = sbase + G2_ASTAGE + a_dst;
            const char* sp1 = (const char*)(Asrc + (c0+1)*32);
            CP16(d1, sp1); CP16(d1+16, sp1+16); CP16(d1+32, sp1+32); CP16(d1+48, sp1+48);
            CP_COMMIT();
        }
        float2 vb[4];
        int kbase = c0*32 + seg*8;
        #pragma unroll
        for (int j = 0; j < 4; j++){
            int kg = kbase + 2*j;
            vb[j] = (kg < KTOT) ? *(const float2*)(Bsrc + c0*32 + 2*j) : make_float2(0.f, 0.f);
        }
        __half2 p0 = __floats2half2_rn(vb[0].x, vb[0].y);
        __half2 p1 = __floats2half2_rn(vb[1].x, vb[1].y);
        __half2 p2 = __floats2half2_rn(vb[2].x, vb[2].y);
        __half2 p3 = __floats2half2_rn(vb[3].x, vb[3].y);
        uint4 u = make_uint4(*(uint32_t*)&p0, *(uint32_t*)&p1, *(uint32_t*)&p2, *(uint32_t*)&p3);
        *(uint4*)(smem + b_dst) = u;
    }

    uint32_t a_row = (uint32_t)(m_w + (lane & 15));
    uint32_t a_koff = ((lane >> 4) & 1)*16;
    uint32_t b_row = (uint32_t)(n_w + ((lane >> 4) & 1)*8 + (lane & 7));
    uint32_t b_koff = ((lane >> 3) & 1)*16;

    for (int c = c0; c < c1; c++){
        int rel = c - c0;
        uint32_t sa = sbase + (uint32_t)(rel % 3)*G2_ASTAGE;
        uint32_t sbB = sbase + (uint32_t)(rel & 1)*G2_BSTAGE;
        bool more = (c + 1 < c1);

        CP_WAIT1();
        __syncthreads();

        if (c + 2 < c1){
            uint32_t d = sbase + (uint32_t)((rel + 2) % 3)*G2_ASTAGE + a_dst;
            const char* sp = (const char*)(Asrc + (c+2)*32);
            CP16(d, sp); CP16(d+16, sp+16); CP16(d+32, sp+32); CP16(d+48, sp+48);
            CP_COMMIT();
        }
        float2 vb[4];
        if (more){
            #pragma unroll
            for (int j = 0; j < 4; j++){
                int kg = (c+1)*32 + seg*8 + 2*j;
                vb[j] = (kg < KTOT) ? *(const float2*)(Bsrc + (c+1)*32 + 2*j) : make_float2(0.f, 0.f);
            }
        }

        #pragma unroll
        for (int ks = 0; ks < 2; ks++){
            uint32_t ksb = ks*32;
            uint32_t Ah[4][4], Bh[2][4];
            #pragma unroll
            for (int mi = 0; mi < 4; mi++){
                uint32_t ad = sa + (a_row + mi*16)*80 + ksb + a_koff;
                LDSM4(Ah[mi], ad);
            }
            #pragma unroll
            for (int ni = 0; ni < 2; ni++){
                uint32_t bd = sbB + G2_BOFF + (b_row + ni*16)*80 + ksb + b_koff;
                LDSM4(Bh[ni], bd);
            }
            #pragma unroll
            for (int mi = 0; mi < 4; mi++)
                #pragma unroll
                for (int nj = 0; nj < 4; nj++){
                    uint32_t* BH = Bh[nj>>1] + 2*(nj&1);
                    MMAF16(acc[mi][nj], Ah[mi], BH[0], BH[1]);
                }
        }

        if (more){
            __half2 p0 = __floats2half2_rn(vb[0].x, vb[0].y);
            __half2 p1 = __floats2half2_rn(vb[1].x, vb[1].y);
            __half2 p2 = __floats2half2_rn(vb[2].x, vb[2].y);
            __half2 p3 = __floats2half2_rn(vb[3].x, vb[3].y);
            uint4 u = make_uint4(*(uint32_t*)&p0, *(uint32_t*)&p1, *(uint32_t*)&p2, *(uint32_t*)&p3);
            *(uint4*)(smem + ((rel+1) & 1)*G2_BSTAGE + b_dst) = u;
        }
    }

    int g = lane >> 2, tig = lane & 3;
    #pragma unroll
    for (int mi = 0; mi < 4; mi++){
        int mrow = m_w + mi*16 + g;
        #pragma unroll
        for (int nj = 0; nj < 4; nj++){
            int ncol = n0 + n_w + nj*8 + 2*tig;
            if (ncol < NH1){
                float* d0 = g_Cp + ((size_t)z*NB + mrow)*NH1 + ncol;
                *(float2*)d0 = make_float2(acc[mi][nj][0], acc[mi][nj][1]);
                float* d1 = d0 + (size_t)8*NH1;
                *(float2*)d1 = make_float2(acc[mi][nj][2], acc[mi][nj][3]);
            }
        }
    }
}

__global__ void k_comb1(const float* __restrict__ b1){
    int i = blockIdx.x*256 + threadIdx.x;
    if (i >= NB*NH1) return;
    int b = i/NH1, j = i - b*NH1;
    float v = 0.f;
    #pragma unroll
    for (int z = 0; z < SPLITK1; z++) v += g_Cp[(size_t)z*NB*NH1 + i];
    v = v * g_att[b] + b1[j];
    g_C[i] = (v > 0.f) ? v : 0.01f*v;
}

// ---------------- small split-K tiled SGEMM for layer 2 ----------------
template<int SPLITK>
__global__ void __launch_bounds__(256) k_gemm(const float* __restrict__ Bmat, int N, int K){
    const float* A = g_C;
    int n0 = blockIdx.x*64, m0 = blockIdx.y*64, z = blockIdx.z;
    int ck = (K + SPLITK - 1)/SPLITK;
    int k0 = z*ck, kend = min(K, k0 + ck);
    __shared__ float As[64][17], Bs[64][17];
    float acc[4][4];
    #pragma unroll
    for (int mi = 0; mi < 4; mi++)
        #pragma unroll
        for (int ni = 0; ni < 4; ni++) acc[mi][ni] = 0.f;
    int tr = threadIdx.x >> 4, tc = threadIdx.x & 15;
    for (int kt = k0; kt < kend; kt += 16){
        #pragma unroll
        for (int l = 0; l < 4; l++){
            int i = threadIdx.x + l*256;
            int rr = i >> 4, cc = i & 15;
            int k = kt + cc;
            As[rr][cc] = (k < kend) ? A[(size_t)(m0+rr)*K + k] : 0.f;
            int j = n0 + rr;
            Bs[rr][cc] = (k < kend && j < N) ? Bmat[(size_t)j*K + k] : 0.f;
        }
        __syncthreads();
        #pragma unroll
        for (int kk = 0; kk < 16; kk++){
            float a[4], bb[4];
            #pragma unroll
            for (int mi = 0; mi < 4; mi++) a[mi]  = As[tr*4+mi][kk];
            #pragma unroll
            for (int ni = 0; ni < 4; ni++) bb[ni] = Bs[tc*4+ni][kk];
            #pragma unroll
            for (int mi = 0; mi < 4; mi++)
                #pragma unroll
                for (int ni = 0; ni < 4; ni++) acc[mi][ni] = fmaf(a[mi], bb[ni], acc[mi][ni]);
        }
        __syncthreads();
    }
    #pragma unroll
    for (int mi = 0; mi < 4; mi++)
        #pragma unroll
        for (int ni = 0; ni < 4; ni++){
            int m = m0 + tr*4 + mi, n = n0 + tc*4 + ni;
            if (n < N) g_Cp[(size_t)z*NB*N + (size_t)m*N + n] = acc[mi][ni];
        }
}

__global__ void k_comb2(const float* __restrict__ b2){
    int i = blockIdx.x*256 + threadIdx.x;
    if (i >= NB*NO) return;
    int j = i % NO;
    float v = b2[j];
    #pragma unroll
    for (int z = 0; z < 8; z++) v += g_Cp[(size_t)z*NB*NO + i];
    g_x1[i] = v;
}

__global__ void k_head(const float* __restrict__ x, const float* __restrict__ rw,
                       const float* __restrict__ rb, float* __restrict__ out){
    int b = blockIdx.x, t = threadIdx.x;
    float x0 = (x[(size_t)b*SXv*(SYv+1) + t*(SYv+1) + SYv] - 400.0f)*0.01f;
    float v = g_x1[b*NO + t]*rw[2*t] + x0*rw[2*t+1];
    __shared__ float s[128];
    s[t] = v; __syncthreads();
    for (int o = 64; o > 0; o >>= 1){ if (t < o) s[t] += s[t+o]; __syncthreads(); }
    if (t == 0) out[b] = s[0] + rb[0];
}

// ---------------- launch ----------------
extern "C" void kernel_launch(void* const* d_in, const int* in_sizes, int n_in,
                              void* d_out, int out_size){
    const float* x      = (const float*)d_in[0];
    const float* p_w    = (const float*)d_in[1];
    const float* p_b    = (const float*)d_in[2];
    const float* sc0_w1 = (const float*)d_in[3];
    const float* sc0_w2 = (const float*)d_in[4];
    const float* sc1_w1 = (const float*)d_in[5];
    const float* sc1_w2 = (const float*)d_in[6];
    const float* mlp0_w1= (const float*)d_in[7];
    const float* mlp0_b1= (const float*)d_in[8];
    const float* mlp0_w2= (const float*)d_in[9];
    const float* mlp0_b2= (const float*)d_in[10];
    const float* mlp1_w1= (const float*)d_in[11];
    const float* mlp1_b1= (const float*)d_in[12];
    const float* mlp1_w2= (const float*)d_in[13];
    const float* mlp1_b2= (const float*)d_in[14];
    const float* w0_w   = (const float*)d_in[15];
    const float* w0_b   = (const float*)d_in[16];
    const float* w1_w   = (const float*)d_in[17];
    const float* w1_b   = (const float*)d_in[18];
    const float* sa_cw  = (const float*)d_in[19];
    const float* sa_cb  = (const float*)d_in[20];
    const float* sa_fw  = (const float*)d_in[21];
    const float* sa_fb  = (const float*)d_in[22];
    const float* o1_w1  = (const float*)d_in[23];
    const float* o1_b1  = (const float*)d_in[24];
    const float* o1_w2  = (const float*)d_in[25];
    const float* o1_b2  = (const float*)d_in[26];
    const float* reg2_w = (const float*)d_in[27];
    const float* reg2_b = (const float*)d_in[28];
    float* out = (float*)d_out;

    cudaFuncSetAttribute(k_gemm1_mma, cudaFuncAttributeMaxDynamicSharedMemorySize, G2_SMEM);
    cudaFuncSetAttribute(k_conv_tc,   cudaFuncAttributeMaxDynamicSharedMemorySize, CV_SMEM);

    k_twiddle<<<28, 256>>>();

    // Fourier block 0
    k_fdft<<<NB*NC, 256>>>(x, p_w, p_b, 1);
    k_mix<<<dim3(NB, 4), 256>>>(sc0_w1, sc0_w2);
    k_idft<<<NB*NC, 256>>>();
    k_fuse<<<dim3((NP+255)/256, NB), 256>>>(mlp0_w1, mlp0_b1, mlp0_w2, mlp0_b2, w0_w, w0_b, 0);

    // Fourier block 1 (fuse also writes fp16 A)
    k_fdft<<<NB*NC, 256>>>(x, p_w, p_b, 0);
    k_mix<<<dim3(NB, 4), 256>>>(sc1_w1, sc1_w2);
    k_idft<<<NB*NC, 256>>>();
    k_fuse<<<dim3((NP+255)/256, NB), 256>>>(mlp1_w1, mlp1_b1, mlp1_w2, mlp1_b2, w1_w, w1_b, 1);

    // ---- fork: spatial attention on side stream (reads g_h fp32) ----
    cudaEventRecord(g_sp.eFuse, 0);
    cudaStreamWaitEvent(g_sp.s2, g_sp.eFuse, 0);
    k_conv_tc<<<dim3(NTILE, NB), 256, CV_SMEM, g_sp.s2>>>(sa_cw, sa_cb);
    k_att<<<1, 256, 0, g_sp.s2>>>(sa_fw, sa_fb);
    cudaEventRecord(g_sp.eAtt, g_sp.s2);

    // main stream: big GEMM
    k_gemm1_mma<<<dim3(44, SPLITK1), 256, G2_SMEM>>>(o1_w1);

    cudaStreamWaitEvent(0, g_sp.eAtt, 0);
    k_comb1<<<(NB*NH1+255)/256, 256>>>(o1_b1);
    k_gemm<8><<<dim3(2, 4, 8), 256>>>(o1_w2, NO, 2808);
    k_comb2<<<(NB*NO+255)/256, 256>>>(o1_b2);
    k_head<<<NB, 128>>>(x, reg2_w, reg2_b, out);
}